// round 11
// baseline (speedup 1.0000x reference)
#include <cuda_runtime.h>
#include <cuda_bf16.h>
#include <cuda_fp16.h>
#include <cstdint>

#define BATCH 4
#define SEQ   2048
#define EMB   1024
#define HS    64
#define MROWS (BATCH * SEQ)     // 8192
#define NCOMB 192               // Wq | Wk | Wv stacked

// Q pre-scale: HS^-0.5 * log2(e)  (softmax done in exp2 domain)
#define QSCALE 0.180336880111f

// ---------------------------------------------------------------------------
// Device scratch (no allocations allowed)
// ---------------------------------------------------------------------------
__device__ __nv_bfloat16 g_Whi[NCOMB * EMB];
__device__ __nv_bfloat16 g_Wlo[NCOMB * EMB];
__device__ __nv_bfloat16 g_Qhi[MROWS * HS];   // pre-scaled by QSCALE
__device__ __nv_bfloat16 g_Qlo[MROWS * HS];
__device__ __nv_bfloat16 g_Khi[MROWS * HS];
__device__ __nv_bfloat16 g_Klo[MROWS * HS];
__device__ __half        g_V16[MROWS * HS];   // single-pass fp16 V
__device__ float g_Opart[6][MROWS * HS];
__device__ float g_mpart[6][MROWS];
__device__ float g_lpart[6][MROWS];
__device__ unsigned g_cnt[BATCH * 32];        // zero-init; self-resetting

// ---------------------------------------------------------------------------
// Helpers
// ---------------------------------------------------------------------------
static __device__ __forceinline__ unsigned smem_u32(const void* p) {
    unsigned a;
    asm("{ .reg .u64 t; cvta.to.shared.u64 t, %1; cvt.u32.u64 %0, t; }"
        : "=r"(a) : "l"(p));
    return a;
}
static __device__ __forceinline__ void ldm_x4(unsigned addr, unsigned r[4]) {
    asm volatile("ldmatrix.sync.aligned.m8n8.x4.shared.b16 {%0,%1,%2,%3}, [%4];"
                 : "=r"(r[0]), "=r"(r[1]), "=r"(r[2]), "=r"(r[3]) : "r"(addr));
}
static __device__ __forceinline__ void ldm_x4t(unsigned addr, unsigned r[4]) {
    asm volatile("ldmatrix.sync.aligned.m8n8.x4.trans.shared.b16 {%0,%1,%2,%3}, [%4];"
                 : "=r"(r[0]), "=r"(r[1]), "=r"(r[2]), "=r"(r[3]) : "r"(addr));
}
static __device__ __forceinline__ void mma_bf16(float c[4], const unsigned a[4],
                                                const unsigned b[2]) {
    asm volatile(
        "mma.sync.aligned.m16n8k16.row.col.f32.bf16.bf16.f32 "
        "{%0,%1,%2,%3}, {%4,%5,%6,%7}, {%8,%9}, {%0,%1,%2,%3};"
        : "+f"(c[0]), "+f"(c[1]), "+f"(c[2]), "+f"(c[3])
        : "r"(a[0]), "r"(a[1]), "r"(a[2]), "r"(a[3]), "r"(b[0]), "r"(b[1]));
}
static __device__ __forceinline__ void mma_f16(float c[4], const unsigned a[4],
                                               const unsigned b[2]) {
    asm volatile(
        "mma.sync.aligned.m16n8k16.row.col.f32.f16.f16.f32 "
        "{%0,%1,%2,%3}, {%4,%5,%6,%7}, {%8,%9}, {%0,%1,%2,%3};"
        : "+f"(c[0]), "+f"(c[1]), "+f"(c[2]), "+f"(c[3])
        : "r"(a[0]), "r"(a[1]), "r"(a[2]), "r"(a[3]), "r"(b[0]), "r"(b[1]));
}
static __device__ __forceinline__ void split_hl(float v0, float v1,
                                                unsigned& hi, unsigned& lo) {
    __nv_bfloat16 h0 = __float2bfloat16(v0), h1 = __float2bfloat16(v1);
    __nv_bfloat162 h = __halves2bfloat162(h0, h1);
    __nv_bfloat162 l = __halves2bfloat162(
        __float2bfloat16(v0 - __bfloat162float(h0)),
        __float2bfloat16(v1 - __bfloat162float(h1)));
    hi = reinterpret_cast<unsigned&>(h);
    lo = reinterpret_cast<unsigned&>(l);
}
static __device__ __forceinline__ unsigned pack_h2(float lo, float hi) {
    unsigned r;
    asm("cvt.rn.f16x2.f32 %0, %1, %2;" : "=r"(r) : "f"(hi), "f"(lo));
    return r;
}
#define CP_ASYNC16(dst, src) \
    asm volatile("cp.async.cg.shared.global [%0], [%1], 16;" :: "r"(dst), "l"(src))
#define CP_COMMIT() asm volatile("cp.async.commit_group;")
#define CP_WAIT0()  asm volatile("cp.async.wait_group 0;")

// ---------------------------------------------------------------------------
// Kernel 0: W -> bf16 hi/lo (R9 config — grid 192, 1 float4/thread)
// ---------------------------------------------------------------------------
__global__ __launch_bounds__(256) void wconv_kernel(
    const float* __restrict__ Wq, const float* __restrict__ Wk,
    const float* __restrict__ Wv)
{
    const int i = blockIdx.x * 256 + threadIdx.x;
    if (i >= NCOMB * EMB / 4) return;
    const int e = i * 4, row = e >> 10, col = e & 1023;
    const float* src = (row < 64)  ? (Wq + (size_t)row * EMB)
                     : (row < 128) ? (Wk + (size_t)(row - 64) * EMB)
                                   : (Wv + (size_t)(row - 128) * EMB);
    float4 v = *(const float4*)(src + col);
    uint2 hp, lp;
    split_hl(v.x, v.y, hp.x, lp.x);
    split_hl(v.z, v.w, hp.y, lp.y);
    ((uint2*)g_Whi)[i] = hp;
    ((uint2*)g_Wlo)[i] = lp;
}

// ---------------------------------------------------------------------------
// Kernel 1: combined QKV GEMM (R9 config). mma.sync bf16 hi/lo, BK=64,
// A+B double-buffered, ONE __syncthreads per chunk. CTA 64x192, grid 128.
// ---------------------------------------------------------------------------
#define AST 72
#define A_STAGE_B 18432              // hi (9216) + lo (9216) per stage
#define B_OFF     36864              // after 2 A stages
#define B_HL_BYTES  27648
#define B_BUF_BYTES 55296            // hi + lo, one stage
#define G_SMEM_BYTES (B_OFF + 2 * B_BUF_BYTES)   // 147456

__global__ __launch_bounds__(256) void qkv_gemm_kernel(const float* __restrict__ x)
{
    extern __shared__ char smc[];
    const unsigned sbase = smem_u32(smc);
    const int tid  = threadIdx.x;
    const int wid  = tid >> 5;
    const int lane = tid & 31;
    const int wm   = wid & 1;
    const int wn   = wid >> 1;
    const int m0   = blockIdx.x * 64;

    float acc[2][6][4];
#pragma unroll
    for (int f = 0; f < 2; f++)
#pragma unroll
        for (int g = 0; g < 6; g++)
#pragma unroll
            for (int e = 0; e < 4; e++) acc[f][g][e] = 0.f;

    const int a_row = wm * 32 + (lane & 15);
    const int a_col = (lane >> 4) * 8;
    const int b_sub = lane >> 3;
    const int b_row = (b_sub >> 1) * 8 + (lane & 7);
    const int b_col = (b_sub & 1) * 8;

    // ---- prologue: A(0) -> smem stage 0; av <- A(1); cp.async B(0) ----
#pragma unroll
    for (int it = 0; it < 4; it++) {
        const int i = tid + it * 256;
        const int row = i >> 4, u = i & 15;
        float4 v = *(const float4*)(x + (size_t)(m0 + row) * EMB + u * 4);
        uint2 hp, lp;
        split_hl(v.x, v.y, hp.x, lp.x);
        split_hl(v.z, v.w, hp.y, lp.y);
        *(uint2*)(smc + (row * AST + u * 4) * 2)        = hp;
        *(uint2*)(smc + 9216 + (row * AST + u * 4) * 2) = lp;
    }
    float4 av[4];
#pragma unroll
    for (int it = 0; it < 4; it++) {
        const int i = tid + it * 256;
        const int row = i >> 4, u = i & 15;
        av[it] = *(const float4*)(x + (size_t)(m0 + row) * EMB + 64 + u * 4);
    }
#pragma unroll
    for (int i = tid; i < 192 * 8; i += 256) {
        const int row = i >> 3, u = i & 7;
        const unsigned d = sbase + B_OFF + (unsigned)(row * AST + u * 8) * 2;
        CP_ASYNC16(d,               g_Whi + (size_t)row * EMB + u * 8);
        CP_ASYNC16(d + B_HL_BYTES,  g_Wlo + (size_t)row * EMB + u * 8);
    }
    CP_COMMIT();

    for (int c = 0; c < 16; c++) {
        CP_WAIT0();            // drain B(c)
        __syncthreads();       // publish B(c) + A(c) stores; frees (c+1)&1 bufs

        if (c + 1 < 16) {
            char* abase = smc + ((c + 1) & 1) * A_STAGE_B;
#pragma unroll
            for (int it = 0; it < 4; it++) {
                const int i = tid + it * 256;
                const int row = i >> 4, u = i & 15;
                uint2 hp, lp;
                split_hl(av[it].x, av[it].y, hp.x, lp.x);
                split_hl(av[it].z, av[it].w, hp.y, lp.y);
                *(uint2*)(abase + (row * AST + u * 4) * 2)        = hp;
                *(uint2*)(abase + 9216 + (row * AST + u * 4) * 2) = lp;
            }
            if (c + 2 < 16) {
                const int c2 = (c + 2) * 64;
#pragma unroll
                for (int it = 0; it < 4; it++) {
                    const int i = tid + it * 256;
                    const int row = i >> 4, u = i & 15;
                    av[it] = *(const float4*)(x + (size_t)(m0 + row) * EMB + c2 + u * 4);
                }
            }
            const int c1 = (c + 1) * 64;
            const unsigned bb = sbase + B_OFF + ((c + 1) & 1) * B_BUF_BYTES;
#pragma unroll
            for (int i = tid; i < 192 * 8; i += 256) {
                const int row = i >> 3, u = i & 7;
                const unsigned d = bb + (unsigned)(row * AST + u * 8) * 2;
                CP_ASYNC16(d,              g_Whi + (size_t)row * EMB + c1 + u * 8);
                CP_ASYNC16(d + B_HL_BYTES, g_Wlo + (size_t)row * EMB + c1 + u * 8);
            }
            CP_COMMIT();
        }

        // compute chunk c
        const unsigned sAhi_u = sbase + (c & 1) * A_STAGE_B;
        const unsigned sAlo_u = sAhi_u + 9216;
        const unsigned sBhi_u = sbase + B_OFF + (c & 1) * B_BUF_BYTES;
        const unsigned sBlo_u = sBhi_u + B_HL_BYTES;

#pragma unroll
        for (int ks = 0; ks < 4; ks++) {
            unsigned ah[2][4], al[2][4], bh[6][2], bl[6][2];
#pragma unroll
            for (int f = 0; f < 2; f++) {
                const unsigned off = ((a_row + f * 16) * AST + a_col + ks * 16) * 2;
                ldm_x4(sAhi_u + off, ah[f]);
                ldm_x4(sAlo_u + off, al[f]);
            }
#pragma unroll
            for (int p = 0; p < 3; p++) {
                const unsigned off =
                    ((wn * 48 + p * 16 + b_row) * AST + b_col + ks * 16) * 2;
                unsigned t[4];
                ldm_x4(sBhi_u + off, t);
                bh[p * 2][0] = t[0]; bh[p * 2][1] = t[1];
                bh[p * 2 + 1][0] = t[2]; bh[p * 2 + 1][1] = t[3];
                ldm_x4(sBlo_u + off, t);
                bl[p * 2][0] = t[0]; bl[p * 2][1] = t[1];
                bl[p * 2 + 1][0] = t[2]; bl[p * 2 + 1][1] = t[3];
            }
#pragma unroll
            for (int f = 0; f < 2; f++)
#pragma unroll
                for (int g = 0; g < 6; g++) {
                    mma_bf16(acc[f][g], ah[f], bh[g]);
                    mma_bf16(acc[f][g], ah[f], bl[g]);
                    mma_bf16(acc[f][g], al[f], bh[g]);
                }
        }
    }

    // Epilogue: Q (bf16 hi/lo, pre-scaled), K (bf16 hi/lo), V (fp16 single)
#pragma unroll
    for (int g = 0; g < 6; g++) {
        const int nblk = wn * 48 + g * 8;
        const int coff = (nblk & 63) + (lane & 3) * 2;
#pragma unroll
        for (int f = 0; f < 2; f++) {
            const int row = m0 + wm * 32 + f * 16 + (lane >> 2);
            if (nblk < 128) {
                __nv_bfloat16* hb = (nblk < 64) ? g_Qhi : g_Khi;
                __nv_bfloat16* lb = (nblk < 64) ? g_Qlo : g_Klo;
                const float sc = (nblk < 64) ? QSCALE : 1.0f;
                unsigned h0, l0, h1, l1;
                split_hl(acc[f][g][0] * sc, acc[f][g][1] * sc, h0, l0);
                split_hl(acc[f][g][2] * sc, acc[f][g][3] * sc, h1, l1);
                *(unsigned*)(hb + (size_t)row * HS + coff)       = h0;
                *(unsigned*)(lb + (size_t)row * HS + coff)       = l0;
                *(unsigned*)(hb + (size_t)(row + 8) * HS + coff) = h1;
                *(unsigned*)(lb + (size_t)(row + 8) * HS + coff) = l1;
            } else {
                *(unsigned*)(g_V16 + (size_t)row * HS + coff) =
                    pack_h2(acc[f][g][0], acc[f][g][1]);
                *(unsigned*)(g_V16 + (size_t)(row + 8) * HS + coff) =
                    pack_h2(acc[f][g][2], acc[f][g][3]);
            }
        }
    }
}

// ---------------------------------------------------------------------------
// Kernel 2: causal flash attention. QK^T bf16 hi/lo (3-pass), PV fp16
// single-pass. exp2 domain. K/V double-buffered, ONE sync per tile.
// Split-K <=6 tiles (ns = ceil((q+1)/6)): 102 chunks/batch, grid 408 =
// one wave at 3 CTAs/SM (smem 73.7KB -> 3 fit). Fused last-CTA merge.
// ---------------------------------------------------------------------------
#define FST 72
#define F_TILE (64 * FST)
#define F_TILE_B (F_TILE * 2)            // 9216
#define KV_STAGE_B (3 * F_TILE_B)        // Khi, Klo, V16 = 27648
#define F_SMEM_BYTES (2 * F_TILE_B + 2 * KV_STAGE_B)   // 73728

__global__ __launch_bounds__(128, 3) void flash_kernel(float* __restrict__ out)
{
    extern __shared__ __nv_bfloat16 fs[];
    __nv_bfloat16* sQh = fs;
    __nv_bfloat16* sQl = sQh + F_TILE;
    __shared__ unsigned s_flag;

    // chunk -> (qblk, part, ns), ns = ceil((q+1)/6), heavy-first
    const int i = blockIdx.x;       // 0..101
    int qblk, part, ns;
    if (i < 12)      { qblk = 31 - (i / 6);            part = i % 6;  ns = 6; }
    else if (i < 42) { int t = i - 12; qblk = 29 - t / 5; part = t % 5; ns = 5; }
    else if (i < 66) { int t = i - 42; qblk = 23 - t / 4; part = t % 4; ns = 4; }
    else if (i < 84) { int t = i - 66; qblk = 17 - t / 3; part = t % 3; ns = 3; }
    else if (i < 96) { int t = i - 84; qblk = 11 - (t >> 1); part = t & 1; ns = 2; }
    else             { int t = i - 96; qblk = 5 - t;   part = 0;      ns = 1; }
    const int b  = blockIdx.y;
    const int nt = qblk + 1;
    const int jb = part * nt / ns;
    const int je = (part + 1) * nt / ns;

    const int tid  = threadIdx.x;
    const int w    = tid >> 5;
    const int lane = tid & 31;
    const size_t base = (size_t)b * SEQ * HS;

    const unsigned sbase = smem_u32(fs);
    const unsigned kv0   = sbase + 2 * F_TILE_B;

#pragma unroll
    for (int k = tid; k < 64 * 8; k += 128) {
        const int row = k >> 3, u = k & 7;
        const size_t gi = base + (size_t)(jb * 64 + row) * HS + u * 8;
        const unsigned d = kv0 + (unsigned)(row * FST + u * 8) * 2;
        CP_ASYNC16(d,                g_Khi + gi);
        CP_ASYNC16(d + F_TILE_B,     g_Klo + gi);
        CP_ASYNC16(d + 2 * F_TILE_B, g_V16 + gi);
    }
    CP_COMMIT();

#pragma unroll
    for (int k = tid; k < 64 * 8; k += 128) {
        const int row = k >> 3, u = k & 7;
        const size_t gi = base + (size_t)(qblk * 64 + row) * HS + u * 8;
        *(uint4*)(sQh + row * FST + u * 8) = *(const uint4*)(g_Qhi + gi);
        *(uint4*)(sQl + row * FST + u * 8) = *(const uint4*)(g_Qlo + gi);
    }
    __syncthreads();

    const unsigned sQh_u = sbase, sQl_u = sbase + F_TILE_B;
    unsigned qh[4][4], ql[4][4];
    {
        const int ar = w * 16 + (lane & 15);
        const int ac = (lane >> 4) * 8;
#pragma unroll
        for (int ks = 0; ks < 4; ks++) {
            const unsigned off = (ar * FST + ks * 16 + ac) * 2;
            ldm_x4(sQh_u + off, qh[ks]);
            ldm_x4(sQl_u + off, ql[ks]);
        }
    }

    float o[8][4];
#pragma unroll
    for (int nf = 0; nf < 8; nf++)
#pragma unroll
        for (int e = 0; e < 4; e++) o[nf][e] = 0.f;
    float mA = -1e30f, mB = -1e30f, lA = 0.f, lB = 0.f;

    const int b_sub = lane >> 3;
    const int kb_row = (b_sub >> 1) * 8 + (lane & 7);
    const int kb_col = (b_sub & 1) * 8;
    const int vb_row = (b_sub & 1) * 8 + (lane & 7);
    const int vb_col = (b_sub >> 1) * 8;

    for (int j = jb; j < je; j++) {
        const int cur = (j - jb) & 1;

        CP_WAIT0();
        __syncthreads();

        if (j + 1 < je) {
            const unsigned nb = kv0 + (cur ^ 1) * KV_STAGE_B;
#pragma unroll
            for (int k = tid; k < 64 * 8; k += 128) {
                const int row = k >> 3, u = k & 7;
                const size_t gi = base + (size_t)((j + 1) * 64 + row) * HS + u * 8;
                const unsigned d = nb + (unsigned)(row * FST + u * 8) * 2;
                CP_ASYNC16(d,                g_Khi + gi);
                CP_ASYNC16(d + F_TILE_B,     g_Klo + gi);
                CP_ASYNC16(d + 2 * F_TILE_B, g_V16 + gi);
            }
            CP_COMMIT();
        }

        const unsigned sKh_u = kv0 + cur * KV_STAGE_B;
        const unsigned sKl_u = sKh_u + F_TILE_B;
        const unsigned sV_u  = sKh_u + 2 * F_TILE_B;

        float s[8][4];
#pragma unroll
        for (int nf = 0; nf < 8; nf++)
#pragma unroll
            for (int e = 0; e < 4; e++) s[nf][e] = 0.f;

#pragma unroll
        for (int ks = 0; ks < 4; ks++) {
            unsigned kh[8][2], kl[8][2];
#pragma unroll
            for (int np = 0; np < 4; np++) {
                const unsigned off = ((np * 16 + kb_row) * FST + ks * 16 + kb_col) * 2;
                unsigned t[4];
                ldm_x4(sKh_u + off, t);
                kh[np * 2][0] = t[0]; kh[np * 2][1] = t[1];
                kh[np * 2 + 1][0] = t[2]; kh[np * 2 + 1][1] = t[3];
                ldm_x4(sKl_u + off, t);
                kl[np * 2][0] = t[0]; kl[np * 2][1] = t[1];
                kl[np * 2 + 1][0] = t[2]; kl[np * 2 + 1][1] = t[3];
            }
#pragma unroll
            for (int nf = 0; nf < 8; nf++) {
                mma_bf16(s[nf], qh[ks], kh[nf]);
                mma_bf16(s[nf], qh[ks], kl[nf]);
                mma_bf16(s[nf], ql[ks], kh[nf]);
            }
        }

        if (j == qblk) {
            const int rA = w * 16 + (lane >> 2);
            const int c0 = (lane & 3) * 2;
#pragma unroll
            for (int nf = 0; nf < 8; nf++) {
                const int c = nf * 8 + c0;
                if (c > rA)         s[nf][0] = -1e30f;
                if (c + 1 > rA)     s[nf][1] = -1e30f;
                if (c > rA + 8)     s[nf][2] = -1e30f;
                if (c + 1 > rA + 8) s[nf][3] = -1e30f;
            }
        }

        float tmA = -1e30f, tmB = -1e30f;
#pragma unroll
        for (int nf = 0; nf < 8; nf++) {
            tmA = fmaxf(tmA, fmaxf(s[nf][0], s[nf][1]));
            tmB = fmaxf(tmB, fmaxf(s[nf][2], s[nf][3]));
        }
#pragma unroll
        for (int off = 1; off < 4; off <<= 1) {
            tmA = fmaxf(tmA, __shfl_xor_sync(0xffffffffu, tmA, off));
            tmB = fmaxf(tmB, __shfl_xor_sync(0xffffffffu, tmB, off));
        }
        const float mnA = fmaxf(mA, tmA), mnB = fmaxf(mB, tmB);
        const float aA = exp2f(mA - mnA), aB = exp2f(mB - mnB);
        mA = mnA; mB = mnB;

        float sumA = 0.f, sumB = 0.f;
#pragma unroll
        for (int nf = 0; nf < 8; nf++) {
            s[nf][0] = exp2f(s[nf][0] - mnA); sumA += s[nf][0];
            s[nf][1] = exp2f(s[nf][1] - mnA); sumA += s[nf][1];
            s[nf][2] = exp2f(s[nf][2] - mnB); sumB += s[nf][2];
            s[nf][3] = exp2f(s[nf][3] - mnB); sumB += s[nf][3];
        }
#pragma unroll
        for (int off = 1; off < 4; off <<= 1) {
            sumA += __shfl_xor_sync(0xffffffffu, sumA, off);
            sumB += __shfl_xor_sync(0xffffffffu, sumB, off);
        }
        lA = lA * aA + sumA;
        lB = lB * aB + sumB;
#pragma unroll
        for (int nf = 0; nf < 8; nf++) {
            o[nf][0] *= aA; o[nf][1] *= aA;
            o[nf][2] *= aB; o[nf][3] *= aB;
        }

#pragma unroll
        for (int ks = 0; ks < 4; ks++) {
            unsigned ap[4];
            ap[0] = pack_h2(s[2 * ks][0],     s[2 * ks][1]);
            ap[1] = pack_h2(s[2 * ks][2],     s[2 * ks][3]);
            ap[2] = pack_h2(s[2 * ks + 1][0], s[2 * ks + 1][1]);
            ap[3] = pack_h2(s[2 * ks + 1][2], s[2 * ks + 1][3]);

            unsigned vh[8][2];
#pragma unroll
            for (int hp = 0; hp < 4; hp++) {
                const unsigned off = ((ks * 16 + vb_row) * FST + hp * 16 + vb_col) * 2;
                unsigned t[4];
                ldm_x4t(sV_u + off, t);
                vh[hp * 2][0] = t[0]; vh[hp * 2][1] = t[1];
                vh[hp * 2 + 1][0] = t[2]; vh[hp * 2 + 1][1] = t[3];
            }
#pragma unroll
            for (int nf = 0; nf < 8; nf++)
                mma_f16(o[nf], ap, vh[nf]);
        }
    }

    const int rA = qblk * 64 + w * 16 + (lane >> 2);
    const size_t grA = (size_t)b * SEQ + rA;
    const size_t grB = grA + 8;
    const int c0 = (lane & 3) * 2;

    if (ns == 1) {
        const float invA = 1.f / lA, invB = 1.f / lB;
#pragma unroll
        for (int nf = 0; nf < 8; nf++) {
            const int c = nf * 8 + c0;
            *(float2*)(out + grA * HS + c) =
                make_float2(o[nf][0] * invA, o[nf][1] * invA);
            *(float2*)(out + grB * HS + c) =
                make_float2(o[nf][2] * invB, o[nf][3] * invB);
        }
        return;
    }

#pragma unroll
    for (int nf = 0; nf < 8; nf++) {
        const int c = nf * 8 + c0;
        *(float2*)(&g_Opart[part][grA * HS + c]) = make_float2(o[nf][0], o[nf][1]);
        *(float2*)(&g_Opart[part][grB * HS + c]) = make_float2(o[nf][2], o[nf][3]);
    }
    if ((lane & 3) == 0) {
        g_mpart[part][grA] = mA; g_lpart[part][grA] = lA;
        g_mpart[part][grB] = mB; g_lpart[part][grB] = lB;
    }

    __threadfence();
    if (tid == 0) {
        const unsigned old = atomicAdd(&g_cnt[b * 32 + qblk], 1);
        s_flag = (old == (unsigned)(ns - 1)) ? 1u : 0u;
    }
    __syncthreads();
    if (s_flag) {
        __threadfence();
#pragma unroll
        for (int it = 0; it < 8; it++) {
            const int slot = tid + it * 128;
            const int rl = slot >> 4, u = slot & 15;
            const size_t gr = (size_t)b * SEQ + qblk * 64 + rl;
            float m = -1e30f;
            for (int p = 0; p < ns; p++) m = fmaxf(m, g_mpart[p][gr]);
            float ap[6], den = 0.f;
            for (int p = 0; p < ns; p++) {
                ap[p] = exp2f(g_mpart[p][gr] - m);
                den += g_lpart[p][gr] * ap[p];
            }
            const float inv = 1.f / den;
            float4 acc = make_float4(0.f, 0.f, 0.f, 0.f);
            for (int p = 0; p < ns; p++) {
                float4 v = ((const float4*)(g_Opart[p] + gr * HS))[u];
                acc.x += v.x * ap[p]; acc.y += v.y * ap[p];
                acc.z += v.z * ap[p]; acc.w += v.w * ap[p];
            }
            acc.x *= inv; acc.y *= inv; acc.z *= inv; acc.w *= inv;
            ((float4*)(out + gr * HS))[u] = acc;
        }
        __syncthreads();
        if (tid == 0) g_cnt[b * 32 + qblk] = 0;
    }
}

// ---------------------------------------------------------------------------

extern "C" void kernel_launch(void* const* d_in, const int* in_sizes, int n_in,
                              void* d_out, int out_size)
{
    const float* x  = (const float*)d_in[0];
    const float* Wq = (const float*)d_in[1];
    const float* Wk = (const float*)d_in[2];
    const float* Wv = (const float*)d_in[3];
    float* out      = (float*)d_out;
    (void)in_sizes; (void)n_in; (void)out_size;

    cudaFuncSetAttribute(qkv_gemm_kernel,
                         cudaFuncAttributeMaxDynamicSharedMemorySize, G_SMEM_BYTES);
    cudaFuncSetAttribute(flash_kernel,
                         cudaFuncAttributeMaxDynamicSharedMemorySize, F_SMEM_BYTES);

    wconv_kernel<<<(NCOMB * EMB / 4 + 255) / 256, 256>>>(Wq, Wk, Wv);
    qkv_gemm_kernel<<<MROWS / 64, 256, G_SMEM_BYTES>>>(x);
    flash_kernel<<<dim3(102, BATCH), 128, F_SMEM_BYTES>>>(out);
}

// round 12
// speedup vs baseline: 1.0907x; 1.0907x over previous
#include <cuda_runtime.h>
#include <cuda_bf16.h>
#include <cuda_fp16.h>
#include <cstdint>

#define BATCH 4
#define SEQ   2048
#define EMB   1024
#define HS    64
#define MROWS (BATCH * SEQ)     // 8192
#define NCOMB 192               // Wq | Wk | Wv stacked

// Q pre-scale: HS^-0.5 * log2(e)  (softmax done in exp2 domain)
#define QSCALE 0.180336880111f

// ---------------------------------------------------------------------------
// Device scratch (no allocations allowed)
// ---------------------------------------------------------------------------
__device__ __nv_bfloat16 g_Whi[NCOMB * EMB];
__device__ __nv_bfloat16 g_Wlo[NCOMB * EMB];
__device__ __nv_bfloat16 g_Qhi[MROWS * HS];   // pre-scaled by QSCALE
__device__ __nv_bfloat16 g_Qlo[MROWS * HS];
__device__ __nv_bfloat16 g_Khi[MROWS * HS];
__device__ __nv_bfloat16 g_Klo[MROWS * HS];
__device__ __half        g_V16[MROWS * HS];   // single-pass fp16 V
__device__ float g_Opart[4][MROWS * HS];
__device__ float g_mpart[4][MROWS];
__device__ float g_lpart[4][MROWS];
__device__ unsigned g_cnt[BATCH * 32];        // zero-init; self-resetting

// ---------------------------------------------------------------------------
// Helpers
// ---------------------------------------------------------------------------
static __device__ __forceinline__ unsigned smem_u32(const void* p) {
    unsigned a;
    asm("{ .reg .u64 t; cvta.to.shared.u64 t, %1; cvt.u32.u64 %0, t; }"
        : "=r"(a) : "l"(p));
    return a;
}
static __device__ __forceinline__ void ldm_x4(unsigned addr, unsigned r[4]) {
    asm volatile("ldmatrix.sync.aligned.m8n8.x4.shared.b16 {%0,%1,%2,%3}, [%4];"
                 : "=r"(r[0]), "=r"(r[1]), "=r"(r[2]), "=r"(r[3]) : "r"(addr));
}
static __device__ __forceinline__ void ldm_x4t(unsigned addr, unsigned r[4]) {
    asm volatile("ldmatrix.sync.aligned.m8n8.x4.trans.shared.b16 {%0,%1,%2,%3}, [%4];"
                 : "=r"(r[0]), "=r"(r[1]), "=r"(r[2]), "=r"(r[3]) : "r"(addr));
}
static __device__ __forceinline__ void mma_bf16(float c[4], const unsigned a[4],
                                                const unsigned b[2]) {
    asm volatile(
        "mma.sync.aligned.m16n8k16.row.col.f32.bf16.bf16.f32 "
        "{%0,%1,%2,%3}, {%4,%5,%6,%7}, {%8,%9}, {%0,%1,%2,%3};"
        : "+f"(c[0]), "+f"(c[1]), "+f"(c[2]), "+f"(c[3])
        : "r"(a[0]), "r"(a[1]), "r"(a[2]), "r"(a[3]), "r"(b[0]), "r"(b[1]));
}
static __device__ __forceinline__ void mma_f16(float c[4], const unsigned a[4],
                                               const unsigned b[2]) {
    asm volatile(
        "mma.sync.aligned.m16n8k16.row.col.f32.f16.f16.f32 "
        "{%0,%1,%2,%3}, {%4,%5,%6,%7}, {%8,%9}, {%0,%1,%2,%3};"
        : "+f"(c[0]), "+f"(c[1]), "+f"(c[2]), "+f"(c[3])
        : "r"(a[0]), "r"(a[1]), "r"(a[2]), "r"(a[3]), "r"(b[0]), "r"(b[1]));
}
static __device__ __forceinline__ void split_hl(float v0, float v1,
                                                unsigned& hi, unsigned& lo) {
    __nv_bfloat16 h0 = __float2bfloat16(v0), h1 = __float2bfloat16(v1);
    __nv_bfloat162 h = __halves2bfloat162(h0, h1);
    __nv_bfloat162 l = __halves2bfloat162(
        __float2bfloat16(v0 - __bfloat162float(h0)),
        __float2bfloat16(v1 - __bfloat162float(h1)));
    hi = reinterpret_cast<unsigned&>(h);
    lo = reinterpret_cast<unsigned&>(l);
}
static __device__ __forceinline__ unsigned pack_h2(float lo, float hi) {
    unsigned r;
    asm("cvt.rn.f16x2.f32 %0, %1, %2;" : "=r"(r) : "f"(hi), "f"(lo));
    return r;
}
static __device__ __forceinline__ float ex2(float x) {
    float y;
    asm("ex2.approx.ftz.f32 %0, %1;" : "=f"(y) : "f"(x));
    return y;
}
#define CP_ASYNC16(dst, src) \
    asm volatile("cp.async.cg.shared.global [%0], [%1], 16;" :: "r"(dst), "l"(src))
#define CP_COMMIT() asm volatile("cp.async.commit_group;")
#define CP_WAIT0()  asm volatile("cp.async.wait_group 0;")

// ---------------------------------------------------------------------------
// Kernel 0: W -> bf16 hi/lo (R9 config)
// ---------------------------------------------------------------------------
__global__ __launch_bounds__(256) void wconv_kernel(
    const float* __restrict__ Wq, const float* __restrict__ Wk,
    const float* __restrict__ Wv)
{
    const int i = blockIdx.x * 256 + threadIdx.x;
    if (i >= NCOMB * EMB / 4) return;
    const int e = i * 4, row = e >> 10, col = e & 1023;
    const float* src = (row < 64)  ? (Wq + (size_t)row * EMB)
                     : (row < 128) ? (Wk + (size_t)(row - 64) * EMB)
                                   : (Wv + (size_t)(row - 128) * EMB);
    float4 v = *(const float4*)(src + col);
    uint2 hp, lp;
    split_hl(v.x, v.y, hp.x, lp.x);
    split_hl(v.z, v.w, hp.y, lp.y);
    ((uint2*)g_Whi)[i] = hp;
    ((uint2*)g_Wlo)[i] = lp;
}

// ---------------------------------------------------------------------------
// Kernel 1: combined QKV GEMM (R9 config). mma.sync bf16 hi/lo, BK=64,
// A+B double-buffered, ONE __syncthreads per chunk. CTA 64x192, grid 128.
// ---------------------------------------------------------------------------
#define AST 72
#define A_STAGE_B 18432
#define B_OFF     36864
#define B_HL_BYTES  27648
#define B_BUF_BYTES 55296
#define G_SMEM_BYTES (B_OFF + 2 * B_BUF_BYTES)   // 147456

__global__ __launch_bounds__(256) void qkv_gemm_kernel(const float* __restrict__ x)
{
    extern __shared__ char smc[];
    const unsigned sbase = smem_u32(smc);
    const int tid  = threadIdx.x;
    const int wid  = tid >> 5;
    const int lane = tid & 31;
    const int wm   = wid & 1;
    const int wn   = wid >> 1;
    const int m0   = blockIdx.x * 64;

    float acc[2][6][4];
#pragma unroll
    for (int f = 0; f < 2; f++)
#pragma unroll
        for (int g = 0; g < 6; g++)
#pragma unroll
            for (int e = 0; e < 4; e++) acc[f][g][e] = 0.f;

    const int a_row = wm * 32 + (lane & 15);
    const int a_col = (lane >> 4) * 8;
    const int b_sub = lane >> 3;
    const int b_row = (b_sub >> 1) * 8 + (lane & 7);
    const int b_col = (b_sub & 1) * 8;

    // ---- prologue: A(0) -> smem stage 0; av <- A(1); cp.async B(0) ----
#pragma unroll
    for (int it = 0; it < 4; it++) {
        const int i = tid + it * 256;
        const int row = i >> 4, u = i & 15;
        float4 v = *(const float4*)(x + (size_t)(m0 + row) * EMB + u * 4);
        uint2 hp, lp;
        split_hl(v.x, v.y, hp.x, lp.x);
        split_hl(v.z, v.w, hp.y, lp.y);
        *(uint2*)(smc + (row * AST + u * 4) * 2)        = hp;
        *(uint2*)(smc + 9216 + (row * AST + u * 4) * 2) = lp;
    }
    float4 av[4];
#pragma unroll
    for (int it = 0; it < 4; it++) {
        const int i = tid + it * 256;
        const int row = i >> 4, u = i & 15;
        av[it] = *(const float4*)(x + (size_t)(m0 + row) * EMB + 64 + u * 4);
    }
#pragma unroll
    for (int i = tid; i < 192 * 8; i += 256) {
        const int row = i >> 3, u = i & 7;
        const unsigned d = sbase + B_OFF + (unsigned)(row * AST + u * 8) * 2;
        CP_ASYNC16(d,               g_Whi + (size_t)row * EMB + u * 8);
        CP_ASYNC16(d + B_HL_BYTES,  g_Wlo + (size_t)row * EMB + u * 8);
    }
    CP_COMMIT();

    for (int c = 0; c < 16; c++) {
        CP_WAIT0();
        __syncthreads();

        if (c + 1 < 16) {
            char* abase = smc + ((c + 1) & 1) * A_STAGE_B;
#pragma unroll
            for (int it = 0; it < 4; it++) {
                const int i = tid + it * 256;
                const int row = i >> 4, u = i & 15;
                uint2 hp, lp;
                split_hl(av[it].x, av[it].y, hp.x, lp.x);
                split_hl(av[it].z, av[it].w, hp.y, lp.y);
                *(uint2*)(abase + (row * AST + u * 4) * 2)        = hp;
                *(uint2*)(abase + 9216 + (row * AST + u * 4) * 2) = lp;
            }
            if (c + 2 < 16) {
                const int c2 = (c + 2) * 64;
#pragma unroll
                for (int it = 0; it < 4; it++) {
                    const int i = tid + it * 256;
                    const int row = i >> 4, u = i & 15;
                    av[it] = *(const float4*)(x + (size_t)(m0 + row) * EMB + c2 + u * 4);
                }
            }
            const int c1 = (c + 1) * 64;
            const unsigned bb = sbase + B_OFF + ((c + 1) & 1) * B_BUF_BYTES;
#pragma unroll
            for (int i = tid; i < 192 * 8; i += 256) {
                const int row = i >> 3, u = i & 7;
                const unsigned d = bb + (unsigned)(row * AST + u * 8) * 2;
                CP_ASYNC16(d,              g_Whi + (size_t)row * EMB + c1 + u * 8);
                CP_ASYNC16(d + B_HL_BYTES, g_Wlo + (size_t)row * EMB + c1 + u * 8);
            }
            CP_COMMIT();
        }

        const unsigned sAhi_u = sbase + (c & 1) * A_STAGE_B;
        const unsigned sAlo_u = sAhi_u + 9216;
        const unsigned sBhi_u = sbase + B_OFF + (c & 1) * B_BUF_BYTES;
        const unsigned sBlo_u = sBhi_u + B_HL_BYTES;

#pragma unroll
        for (int ks = 0; ks < 4; ks++) {
            unsigned ah[2][4], al[2][4], bh[6][2], bl[6][2];
#pragma unroll
            for (int f = 0; f < 2; f++) {
                const unsigned off = ((a_row + f * 16) * AST + a_col + ks * 16) * 2;
                ldm_x4(sAhi_u + off, ah[f]);
                ldm_x4(sAlo_u + off, al[f]);
            }
#pragma unroll
            for (int p = 0; p < 3; p++) {
                const unsigned off =
                    ((wn * 48 + p * 16 + b_row) * AST + b_col + ks * 16) * 2;
                unsigned t[4];
                ldm_x4(sBhi_u + off, t);
                bh[p * 2][0] = t[0]; bh[p * 2][1] = t[1];
                bh[p * 2 + 1][0] = t[2]; bh[p * 2 + 1][1] = t[3];
                ldm_x4(sBlo_u + off, t);
                bl[p * 2][0] = t[0]; bl[p * 2][1] = t[1];
                bl[p * 2 + 1][0] = t[2]; bl[p * 2 + 1][1] = t[3];
            }
#pragma unroll
            for (int f = 0; f < 2; f++)
#pragma unroll
                for (int g = 0; g < 6; g++) {
                    mma_bf16(acc[f][g], ah[f], bh[g]);
                    mma_bf16(acc[f][g], ah[f], bl[g]);
                    mma_bf16(acc[f][g], al[f], bh[g]);
                }
        }
    }

    // Epilogue: Q (bf16 hi/lo, pre-scaled), K (bf16 hi/lo), V (fp16 single)
#pragma unroll
    for (int g = 0; g < 6; g++) {
        const int nblk = wn * 48 + g * 8;
        const int coff = (nblk & 63) + (lane & 3) * 2;
#pragma unroll
        for (int f = 0; f < 2; f++) {
            const int row = m0 + wm * 32 + f * 16 + (lane >> 2);
            if (nblk < 128) {
                __nv_bfloat16* hb = (nblk < 64) ? g_Qhi : g_Khi;
                __nv_bfloat16* lb = (nblk < 64) ? g_Qlo : g_Klo;
                const float sc = (nblk < 64) ? QSCALE : 1.0f;
                unsigned h0, l0, h1, l1;
                split_hl(acc[f][g][0] * sc, acc[f][g][1] * sc, h0, l0);
                split_hl(acc[f][g][2] * sc, acc[f][g][3] * sc, h1, l1);
                *(unsigned*)(hb + (size_t)row * HS + coff)       = h0;
                *(unsigned*)(lb + (size_t)row * HS + coff)       = l0;
                *(unsigned*)(hb + (size_t)(row + 8) * HS + coff) = h1;
                *(unsigned*)(lb + (size_t)(row + 8) * HS + coff) = l1;
            } else {
                *(unsigned*)(g_V16 + (size_t)row * HS + coff) =
                    pack_h2(acc[f][g][0], acc[f][g][1]);
                *(unsigned*)(g_V16 + (size_t)(row + 8) * HS + coff) =
                    pack_h2(acc[f][g][2], acc[f][g][3]);
            }
        }
    }
}

// ---------------------------------------------------------------------------
// Kernel 2: causal flash attention (R9 config + V-hoist + raw ex2).
// QK^T bf16 hi/lo (3-pass), PV fp16 single-pass. K/V double-buffered, ONE
// sync per tile. Split-K <=9 tiles, grid 296 = one wave at 2 CTAs/SM.
// V fragments loaded BEFORE softmax so LDS overlaps the MUFU chain.
// ---------------------------------------------------------------------------
#define FST 72
#define F_TILE (64 * FST)
#define F_TILE_B (F_TILE * 2)            // 9216
#define KV_STAGE_B (3 * F_TILE_B)        // Khi, Klo, V16 = 27648
#define F_SMEM_BYTES (2 * F_TILE_B + 2 * KV_STAGE_B)   // 73728

__global__ __launch_bounds__(128, 2) void flash_kernel(float* __restrict__ out)
{
    extern __shared__ __nv_bfloat16 fs[];
    __nv_bfloat16* sQh = fs;
    __nv_bfloat16* sQl = sQh + F_TILE;
    __shared__ unsigned s_flag;

    // chunk -> (qblk, part, ns), ns = ceil((q+1)/9), heavy-first
    const int i = blockIdx.x;       // 0..73
    int qblk, part, ns;
    if (i < 20)      { qblk = 31 - (i >> 2); part = i & 3; ns = 4; }
    else if (i < 47) { int t = i - 20; qblk = 26 - t / 3; part = t % 3; ns = 3; }
    else if (i < 65) { int t = i - 47; qblk = 17 - (t >> 1); part = t & 1; ns = 2; }
    else             { int t = i - 65; qblk = 8 - t; part = 0; ns = 1; }
    const int b  = blockIdx.y;
    const int nt = qblk + 1;
    const int jb = part * nt / ns;
    const int je = (part + 1) * nt / ns;

    const int tid  = threadIdx.x;
    const int w    = tid >> 5;
    const int lane = tid & 31;
    const size_t base = (size_t)b * SEQ * HS;

    const unsigned sbase = smem_u32(fs);
    const unsigned kv0   = sbase + 2 * F_TILE_B;

#pragma unroll
    for (int k = tid; k < 64 * 8; k += 128) {
        const int row = k >> 3, u = k & 7;
        const size_t gi = base + (size_t)(jb * 64 + row) * HS + u * 8;
        const unsigned d = kv0 + (unsigned)(row * FST + u * 8) * 2;
        CP_ASYNC16(d,                g_Khi + gi);
        CP_ASYNC16(d + F_TILE_B,     g_Klo + gi);
        CP_ASYNC16(d + 2 * F_TILE_B, g_V16 + gi);
    }
    CP_COMMIT();

#pragma unroll
    for (int k = tid; k < 64 * 8; k += 128) {
        const int row = k >> 3, u = k & 7;
        const size_t gi = base + (size_t)(qblk * 64 + row) * HS + u * 8;
        *(uint4*)(sQh + row * FST + u * 8) = *(const uint4*)(g_Qhi + gi);
        *(uint4*)(sQl + row * FST + u * 8) = *(const uint4*)(g_Qlo + gi);
    }
    __syncthreads();

    const unsigned sQh_u = sbase, sQl_u = sbase + F_TILE_B;
    unsigned qh[4][4], ql[4][4];
    {
        const int ar = w * 16 + (lane & 15);
        const int ac = (lane >> 4) * 8;
#pragma unroll
        for (int ks = 0; ks < 4; ks++) {
            const unsigned off = (ar * FST + ks * 16 + ac) * 2;
            ldm_x4(sQh_u + off, qh[ks]);
            ldm_x4(sQl_u + off, ql[ks]);
        }
    }

    float o[8][4];
#pragma unroll
    for (int nf = 0; nf < 8; nf++)
#pragma unroll
        for (int e = 0; e < 4; e++) o[nf][e] = 0.f;
    float mA = -1e30f, mB = -1e30f, lA = 0.f, lB = 0.f;

    const int b_sub = lane >> 3;
    const int kb_row = (b_sub >> 1) * 8 + (lane & 7);
    const int kb_col = (b_sub & 1) * 8;
    const int vb_row = (b_sub & 1) * 8 + (lane & 7);
    const int vb_col = (b_sub >> 1) * 8;

    for (int j = jb; j < je; j++) {
        const int cur = (j - jb) & 1;

        CP_WAIT0();
        __syncthreads();

        if (j + 1 < je) {
            const unsigned nb = kv0 + (cur ^ 1) * KV_STAGE_B;
#pragma unroll
            for (int k = tid; k < 64 * 8; k += 128) {
                const int row = k >> 3, u = k & 7;
                const size_t gi = base + (size_t)((j + 1) * 64 + row) * HS + u * 8;
                const unsigned d = nb + (unsigned)(row * FST + u * 8) * 2;
                CP_ASYNC16(d,                g_Khi + gi);
                CP_ASYNC16(d + F_TILE_B,     g_Klo + gi);
                CP_ASYNC16(d + 2 * F_TILE_B, g_V16 + gi);
            }
            CP_COMMIT();
        }

        const unsigned sKh_u = kv0 + cur * KV_STAGE_B;
        const unsigned sKl_u = sKh_u + F_TILE_B;
        const unsigned sV_u  = sKh_u + 2 * F_TILE_B;

        float s[8][4];
#pragma unroll
        for (int nf = 0; nf < 8; nf++)
#pragma unroll
            for (int e = 0; e < 4; e++) s[nf][e] = 0.f;

#pragma unroll
        for (int ks = 0; ks < 4; ks++) {
            unsigned kh[8][2], kl[8][2];
#pragma unroll
            for (int np = 0; np < 4; np++) {
                const unsigned off = ((np * 16 + kb_row) * FST + ks * 16 + kb_col) * 2;
                unsigned t[4];
                ldm_x4(sKh_u + off, t);
                kh[np * 2][0] = t[0]; kh[np * 2][1] = t[1];
                kh[np * 2 + 1][0] = t[2]; kh[np * 2 + 1][1] = t[3];
                ldm_x4(sKl_u + off, t);
                kl[np * 2][0] = t[0]; kl[np * 2][1] = t[1];
                kl[np * 2 + 1][0] = t[2]; kl[np * 2 + 1][1] = t[3];
            }
#pragma unroll
            for (int nf = 0; nf < 8; nf++) {
                mma_bf16(s[nf], qh[ks], kh[nf]);
                mma_bf16(s[nf], qh[ks], kl[nf]);
                mma_bf16(s[nf], ql[ks], kh[nf]);
            }
        }

        // Hoisted V-fragment loads: independent of S; LDS latency overlaps
        // the softmax MUFU chain below.
        unsigned vh[4][8][2];
#pragma unroll
        for (int ks = 0; ks < 4; ks++)
#pragma unroll
            for (int hp = 0; hp < 4; hp++) {
                const unsigned off = ((ks * 16 + vb_row) * FST + hp * 16 + vb_col) * 2;
                unsigned t[4];
                ldm_x4t(sV_u + off, t);
                vh[ks][hp * 2][0] = t[0]; vh[ks][hp * 2][1] = t[1];
                vh[ks][hp * 2 + 1][0] = t[2]; vh[ks][hp * 2 + 1][1] = t[3];
            }

        if (j == qblk) {
            const int rA = w * 16 + (lane >> 2);
            const int c0 = (lane & 3) * 2;
#pragma unroll
            for (int nf = 0; nf < 8; nf++) {
                const int c = nf * 8 + c0;
                if (c > rA)         s[nf][0] = -1e30f;
                if (c + 1 > rA)     s[nf][1] = -1e30f;
                if (c > rA + 8)     s[nf][2] = -1e30f;
                if (c + 1 > rA + 8) s[nf][3] = -1e30f;
            }
        }

        float tmA = -1e30f, tmB = -1e30f;
#pragma unroll
        for (int nf = 0; nf < 8; nf++) {
            tmA = fmaxf(tmA, fmaxf(s[nf][0], s[nf][1]));
            tmB = fmaxf(tmB, fmaxf(s[nf][2], s[nf][3]));
        }
#pragma unroll
        for (int off = 1; off < 4; off <<= 1) {
            tmA = fmaxf(tmA, __shfl_xor_sync(0xffffffffu, tmA, off));
            tmB = fmaxf(tmB, __shfl_xor_sync(0xffffffffu, tmB, off));
        }
        const float mnA = fmaxf(mA, tmA), mnB = fmaxf(mB, tmB);
        const float aA = ex2(mA - mnA), aB = ex2(mB - mnB);
        mA = mnA; mB = mnB;

        float sumA = 0.f, sumB = 0.f;
#pragma unroll
        for (int nf = 0; nf < 8; nf++) {
            s[nf][0] = ex2(s[nf][0] - mnA); sumA += s[nf][0];
            s[nf][1] = ex2(s[nf][1] - mnA); sumA += s[nf][1];
            s[nf][2] = ex2(s[nf][2] - mnB); sumB += s[nf][2];
            s[nf][3] = ex2(s[nf][3] - mnB); sumB += s[nf][3];
        }
#pragma unroll
        for (int off = 1; off < 4; off <<= 1) {
            sumA += __shfl_xor_sync(0xffffffffu, sumA, off);
            sumB += __shfl_xor_sync(0xffffffffu, sumB, off);
        }
        lA = lA * aA + sumA;
        lB = lB * aB + sumB;
#pragma unroll
        for (int nf = 0; nf < 8; nf++) {
            o[nf][0] *= aA; o[nf][1] *= aA;
            o[nf][2] *= aB; o[nf][3] *= aB;
        }

#pragma unroll
        for (int ks = 0; ks < 4; ks++) {
            unsigned ap[4];
            ap[0] = pack_h2(s[2 * ks][0],     s[2 * ks][1]);
            ap[1] = pack_h2(s[2 * ks][2],     s[2 * ks][3]);
            ap[2] = pack_h2(s[2 * ks + 1][0], s[2 * ks + 1][1]);
            ap[3] = pack_h2(s[2 * ks + 1][2], s[2 * ks + 1][3]);
#pragma unroll
            for (int nf = 0; nf < 8; nf++)
                mma_f16(o[nf], ap, vh[ks][nf]);
        }
    }

    const int rA = qblk * 64 + w * 16 + (lane >> 2);
    const size_t grA = (size_t)b * SEQ + rA;
    const size_t grB = grA + 8;
    const int c0 = (lane & 3) * 2;

    if (ns == 1) {
        const float invA = 1.f / lA, invB = 1.f / lB;
#pragma unroll
        for (int nf = 0; nf < 8; nf++) {
            const int c = nf * 8 + c0;
            *(float2*)(out + grA * HS + c) =
                make_float2(o[nf][0] * invA, o[nf][1] * invA);
            *(float2*)(out + grB * HS + c) =
                make_float2(o[nf][2] * invB, o[nf][3] * invB);
        }
        return;
    }

#pragma unroll
    for (int nf = 0; nf < 8; nf++) {
        const int c = nf * 8 + c0;
        *(float2*)(&g_Opart[part][grA * HS + c]) = make_float2(o[nf][0], o[nf][1]);
        *(float2*)(&g_Opart[part][grB * HS + c]) = make_float2(o[nf][2], o[nf][3]);
    }
    if ((lane & 3) == 0) {
        g_mpart[part][grA] = mA; g_lpart[part][grA] = lA;
        g_mpart[part][grB] = mB; g_lpart[part][grB] = lB;
    }

    __threadfence();
    if (tid == 0) {
        const unsigned old = atomicAdd(&g_cnt[b * 32 + qblk], 1);
        s_flag = (old == (unsigned)(ns - 1)) ? 1u : 0u;
    }
    __syncthreads();
    if (s_flag) {
        __threadfence();
#pragma unroll
        for (int it = 0; it < 8; it++) {
            const int slot = tid + it * 128;
            const int rl = slot >> 4, u = slot & 15;
            const size_t gr = (size_t)b * SEQ + qblk * 64 + rl;
            float m = -1e30f;
            for (int p = 0; p < ns; p++) m = fmaxf(m, g_mpart[p][gr]);
            float ap[4], den = 0.f;
            for (int p = 0; p < ns; p++) {
                ap[p] = ex2(g_mpart[p][gr] - m);
                den += g_lpart[p][gr] * ap[p];
            }
            const float inv = 1.f / den;
            float4 acc = make_float4(0.f, 0.f, 0.f, 0.f);
            for (int p = 0; p < ns; p++) {
                float4 v = ((const float4*)(g_Opart[p] + gr * HS))[u];
                acc.x += v.x * ap[p]; acc.y += v.y * ap[p];
                acc.z += v.z * ap[p]; acc.w += v.w * ap[p];
            }
            acc.x *= inv; acc.y *= inv; acc.z *= inv; acc.w *= inv;
            ((float4*)(out + gr * HS))[u] = acc;
        }
        __syncthreads();
        if (tid == 0) g_cnt[b * 32 + qblk] = 0;
    }
}

// ---------------------------------------------------------------------------

extern "C" void kernel_launch(void* const* d_in, const int* in_sizes, int n_in,
                              void* d_out, int out_size)
{
    const float* x  = (const float*)d_in[0];
    const float* Wq = (const float*)d_in[1];
    const float* Wk = (const float*)d_in[2];
    const float* Wv = (const float*)d_in[3];
    float* out      = (float*)d_out;
    (void)in_sizes; (void)n_in; (void)out_size;

    cudaFuncSetAttribute(qkv_gemm_kernel,
                         cudaFuncAttributeMaxDynamicSharedMemorySize, G_SMEM_BYTES);
    cudaFuncSetAttribute(flash_kernel,
                         cudaFuncAttributeMaxDynamicSharedMemorySize, F_SMEM_BYTES);

    wconv_kernel<<<(NCOMB * EMB / 4 + 255) / 256, 256>>>(Wq, Wk, Wv);
    qkv_gemm_kernel<<<MROWS / 64, 256, G_SMEM_BYTES>>>(x);
    flash_kernel<<<dim3(74, BATCH), 128, F_SMEM_BYTES>>>(out);
}

// round 14
// speedup vs baseline: 1.1676x; 1.0705x over previous
#include <cuda_runtime.h>
#include <cuda_bf16.h>
#include <cuda_fp16.h>
#include <cstdint>

#define BATCH 4
#define SEQ   2048
#define EMB   1024
#define HS    64
#define MROWS (BATCH * SEQ)     // 8192
#define NCOMB 192               // Wq | Wk | Wv stacked

// Q pre-scale: HS^-0.5 * log2(e)  (softmax done in exp2 domain)
#define QSCALE 0.180336880111f

// ---------------------------------------------------------------------------
// Device scratch (no allocations allowed)
// ---------------------------------------------------------------------------
__device__ __nv_bfloat16 g_Whi[NCOMB * EMB];
__device__ __nv_bfloat16 g_Wlo[NCOMB * EMB];
__device__ __half g_Qhi[MROWS * HS];   // fp16 hi/lo, pre-scaled by QSCALE
__device__ __half g_Qlo[MROWS * HS];
__device__ __half g_K16[MROWS * HS];   // single-pass fp16 K
__device__ __half g_V16[MROWS * HS];   // single-pass fp16 V
__device__ float g_Opart[4][MROWS * HS];
__device__ float g_mpart[4][MROWS];
__device__ float g_lpart[4][MROWS];
__device__ unsigned g_cnt[BATCH * 32];        // zero-init; self-resetting

// ---------------------------------------------------------------------------
// Helpers
// ---------------------------------------------------------------------------
static __device__ __forceinline__ unsigned smem_u32(const void* p) {
    unsigned a;
    asm("{ .reg .u64 t; cvta.to.shared.u64 t, %1; cvt.u32.u64 %0, t; }"
        : "=r"(a) : "l"(p));
    return a;
}
static __device__ __forceinline__ void ldm_x4(unsigned addr, unsigned r[4]) {
    asm volatile("ldmatrix.sync.aligned.m8n8.x4.shared.b16 {%0,%1,%2,%3}, [%4];"
                 : "=r"(r[0]), "=r"(r[1]), "=r"(r[2]), "=r"(r[3]) : "r"(addr));
}
static __device__ __forceinline__ void ldm_x4t(unsigned addr, unsigned r[4]) {
    asm volatile("ldmatrix.sync.aligned.m8n8.x4.trans.shared.b16 {%0,%1,%2,%3}, [%4];"
                 : "=r"(r[0]), "=r"(r[1]), "=r"(r[2]), "=r"(r[3]) : "r"(addr));
}
static __device__ __forceinline__ void mma_bf16(float c[4], const unsigned a[4],
                                                const unsigned b[2]) {
    asm volatile(
        "mma.sync.aligned.m16n8k16.row.col.f32.bf16.bf16.f32 "
        "{%0,%1,%2,%3}, {%4,%5,%6,%7}, {%8,%9}, {%0,%1,%2,%3};"
        : "+f"(c[0]), "+f"(c[1]), "+f"(c[2]), "+f"(c[3])
        : "r"(a[0]), "r"(a[1]), "r"(a[2]), "r"(a[3]), "r"(b[0]), "r"(b[1]));
}
static __device__ __forceinline__ void mma_f16(float c[4], const unsigned a[4],
                                               const unsigned b[2]) {
    asm volatile(
        "mma.sync.aligned.m16n8k16.row.col.f32.f16.f16.f32 "
        "{%0,%1,%2,%3}, {%4,%5,%6,%7}, {%8,%9}, {%0,%1,%2,%3};"
        : "+f"(c[0]), "+f"(c[1]), "+f"(c[2]), "+f"(c[3])
        : "r"(a[0]), "r"(a[1]), "r"(a[2]), "r"(a[3]), "r"(b[0]), "r"(b[1]));
}
static __device__ __forceinline__ void split_hl(float v0, float v1,
                                                unsigned& hi, unsigned& lo) {
    __nv_bfloat16 h0 = __float2bfloat16(v0), h1 = __float2bfloat16(v1);
    __nv_bfloat162 h = __halves2bfloat162(h0, h1);
    __nv_bfloat162 l = __halves2bfloat162(
        __float2bfloat16(v0 - __bfloat162float(h0)),
        __float2bfloat16(v1 - __bfloat162float(h1)));
    hi = reinterpret_cast<unsigned&>(h);
    lo = reinterpret_cast<unsigned&>(l);
}
static __device__ __forceinline__ void split_hl_f16(float v0, float v1,
                                                    unsigned& hi, unsigned& lo) {
    __half h0 = __float2half(v0), h1 = __float2half(v1);
    __half2 h = __halves2half2(h0, h1);
    __half2 l = __halves2half2(__float2half(v0 - __half2float(h0)),
                               __float2half(v1 - __half2float(h1)));
    hi = reinterpret_cast<unsigned&>(h);
    lo = reinterpret_cast<unsigned&>(l);
}
static __device__ __forceinline__ unsigned pack_h2(float lo, float hi) {
    unsigned r;
    asm("cvt.rn.f16x2.f32 %0, %1, %2;" : "=r"(r) : "f"(hi), "f"(lo));
    return r;
}
static __device__ __forceinline__ float ex2(float x) {
    float y;
    asm("ex2.approx.ftz.f32 %0, %1;" : "=f"(y) : "f"(x));
    return y;
}
#define CP_ASYNC16(dst, src) \
    asm volatile("cp.async.cg.shared.global [%0], [%1], 16;" :: "r"(dst), "l"(src))
#define CP_COMMIT() asm volatile("cp.async.commit_group;")
#define CP_WAIT0()  asm volatile("cp.async.wait_group 0;")

// ---------------------------------------------------------------------------
// Kernel 0: W -> bf16 hi/lo
// ---------------------------------------------------------------------------
__global__ __launch_bounds__(256) void wconv_kernel(
    const float* __restrict__ Wq, const float* __restrict__ Wk,
    const float* __restrict__ Wv)
{
    const int i = blockIdx.x * 256 + threadIdx.x;
    if (i >= NCOMB * EMB / 4) return;
    const int e = i * 4, row = e >> 10, col = e & 1023;
    const float* src = (row < 64)  ? (Wq + (size_t)row * EMB)
                     : (row < 128) ? (Wk + (size_t)(row - 64) * EMB)
                                   : (Wv + (size_t)(row - 128) * EMB);
    float4 v = *(const float4*)(src + col);
    uint2 hp, lp;
    split_hl(v.x, v.y, hp.x, lp.x);
    split_hl(v.z, v.w, hp.y, lp.y);
    ((uint2*)g_Whi)[i] = hp;
    ((uint2*)g_Wlo)[i] = lp;
}

// ---------------------------------------------------------------------------
// Kernel 1: combined QKV GEMM (R9 config). mma.sync bf16 hi/lo, BK=64,
// A+B double-buffered, ONE __syncthreads per chunk. CTA 64x192, grid 128.
// Epilogue: Q fp16 hi/lo (pre-scaled), K fp16 single, V fp16 single.
// ---------------------------------------------------------------------------
#define AST 72
#define A_STAGE_B 18432
#define B_OFF     36864
#define B_HL_BYTES  27648
#define B_BUF_BYTES 55296
#define G_SMEM_BYTES (B_OFF + 2 * B_BUF_BYTES)   // 147456

__global__ __launch_bounds__(256) void qkv_gemm_kernel(const float* __restrict__ x)
{
    extern __shared__ char smc[];
    const unsigned sbase = smem_u32(smc);
    const int tid  = threadIdx.x;
    const int wid  = tid >> 5;
    const int lane = tid & 31;
    const int wm   = wid & 1;
    const int wn   = wid >> 1;
    const int m0   = blockIdx.x * 64;

    float acc[2][6][4];
#pragma unroll
    for (int f = 0; f < 2; f++)
#pragma unroll
        for (int g = 0; g < 6; g++)
#pragma unroll
            for (int e = 0; e < 4; e++) acc[f][g][e] = 0.f;

    const int a_row = wm * 32 + (lane & 15);
    const int a_col = (lane >> 4) * 8;
    const int b_sub = lane >> 3;
    const int b_row = (b_sub >> 1) * 8 + (lane & 7);
    const int b_col = (b_sub & 1) * 8;

    // ---- prologue: A(0) -> smem stage 0; av <- A(1); cp.async B(0) ----
#pragma unroll
    for (int it = 0; it < 4; it++) {
        const int i = tid + it * 256;
        const int row = i >> 4, u = i & 15;
        float4 v = *(const float4*)(x + (size_t)(m0 + row) * EMB + u * 4);
        uint2 hp, lp;
        split_hl(v.x, v.y, hp.x, lp.x);
        split_hl(v.z, v.w, hp.y, lp.y);
        *(uint2*)(smc + (row * AST + u * 4) * 2)        = hp;
        *(uint2*)(smc + 9216 + (row * AST + u * 4) * 2) = lp;
    }
    float4 av[4];
#pragma unroll
    for (int it = 0; it < 4; it++) {
        const int i = tid + it * 256;
        const int row = i >> 4, u = i & 15;
        av[it] = *(const float4*)(x + (size_t)(m0 + row) * EMB + 64 + u * 4);
    }
#pragma unroll
    for (int i = tid; i < 192 * 8; i += 256) {
        const int row = i >> 3, u = i & 7;
        const unsigned d = sbase + B_OFF + (unsigned)(row * AST + u * 8) * 2;
        CP_ASYNC16(d,               g_Whi + (size_t)row * EMB + u * 8);
        CP_ASYNC16(d + B_HL_BYTES,  g_Wlo + (size_t)row * EMB + u * 8);
    }
    CP_COMMIT();

    for (int c = 0; c < 16; c++) {
        CP_WAIT0();
        __syncthreads();

        if (c + 1 < 16) {
            char* abase = smc + ((c + 1) & 1) * A_STAGE_B;
#pragma unroll
            for (int it = 0; it < 4; it++) {
                const int i = tid + it * 256;
                const int row = i >> 4, u = i & 15;
                uint2 hp, lp;
                split_hl(av[it].x, av[it].y, hp.x, lp.x);
                split_hl(av[it].z, av[it].w, hp.y, lp.y);
                *(uint2*)(abase + (row * AST + u * 4) * 2)        = hp;
                *(uint2*)(abase + 9216 + (row * AST + u * 4) * 2) = lp;
            }
            if (c + 2 < 16) {
                const int c2 = (c + 2) * 64;
#pragma unroll
                for (int it = 0; it < 4; it++) {
                    const int i = tid + it * 256;
                    const int row = i >> 4, u = i & 15;
                    av[it] = *(const float4*)(x + (size_t)(m0 + row) * EMB + c2 + u * 4);
                }
            }
            const int c1 = (c + 1) * 64;
            const unsigned bb = sbase + B_OFF + ((c + 1) & 1) * B_BUF_BYTES;
#pragma unroll
            for (int i = tid; i < 192 * 8; i += 256) {
                const int row = i >> 3, u = i & 7;
                const unsigned d = bb + (unsigned)(row * AST + u * 8) * 2;
                CP_ASYNC16(d,              g_Whi + (size_t)row * EMB + c1 + u * 8);
                CP_ASYNC16(d + B_HL_BYTES, g_Wlo + (size_t)row * EMB + c1 + u * 8);
            }
            CP_COMMIT();
        }

        const unsigned sAhi_u = sbase + (c & 1) * A_STAGE_B;
        const unsigned sAlo_u = sAhi_u + 9216;
        const unsigned sBhi_u = sbase + B_OFF + (c & 1) * B_BUF_BYTES;
        const unsigned sBlo_u = sBhi_u + B_HL_BYTES;

#pragma unroll
        for (int ks = 0; ks < 4; ks++) {
            unsigned ah[2][4], al[2][4], bh[6][2], bl[6][2];
#pragma unroll
            for (int f = 0; f < 2; f++) {
                const unsigned off = ((a_row + f * 16) * AST + a_col + ks * 16) * 2;
                ldm_x4(sAhi_u + off, ah[f]);
                ldm_x4(sAlo_u + off, al[f]);
            }
#pragma unroll
            for (int p = 0; p < 3; p++) {
                const unsigned off =
                    ((wn * 48 + p * 16 + b_row) * AST + b_col + ks * 16) * 2;
                unsigned t[4];
                ldm_x4(sBhi_u + off, t);
                bh[p * 2][0] = t[0]; bh[p * 2][1] = t[1];
                bh[p * 2 + 1][0] = t[2]; bh[p * 2 + 1][1] = t[3];
                ldm_x4(sBlo_u + off, t);
                bl[p * 2][0] = t[0]; bl[p * 2][1] = t[1];
                bl[p * 2 + 1][0] = t[2]; bl[p * 2 + 1][1] = t[3];
            }
#pragma unroll
            for (int f = 0; f < 2; f++)
#pragma unroll
                for (int g = 0; g < 6; g++) {
                    mma_bf16(acc[f][g], ah[f], bh[g]);
                    mma_bf16(acc[f][g], ah[f], bl[g]);
                    mma_bf16(acc[f][g], al[f], bh[g]);
                }
        }
    }

    // Epilogue
#pragma unroll
    for (int g = 0; g < 6; g++) {
        const int nblk = wn * 48 + g * 8;
        const int coff = (nblk & 63) + (lane & 3) * 2;
#pragma unroll
        for (int f = 0; f < 2; f++) {
            const int row = m0 + wm * 32 + f * 16 + (lane >> 2);
            if (nblk < 64) {            // Q: fp16 hi/lo, pre-scaled
                unsigned h0, l0, h1, l1;
                split_hl_f16(acc[f][g][0] * QSCALE, acc[f][g][1] * QSCALE, h0, l0);
                split_hl_f16(acc[f][g][2] * QSCALE, acc[f][g][3] * QSCALE, h1, l1);
                *(unsigned*)(g_Qhi + (size_t)row * HS + coff)       = h0;
                *(unsigned*)(g_Qlo + (size_t)row * HS + coff)       = l0;
                *(unsigned*)(g_Qhi + (size_t)(row + 8) * HS + coff) = h1;
                *(unsigned*)(g_Qlo + (size_t)(row + 8) * HS + coff) = l1;
            } else if (nblk < 128) {    // K: single fp16
                *(unsigned*)(g_K16 + (size_t)row * HS + coff) =
                    pack_h2(acc[f][g][0], acc[f][g][1]);
                *(unsigned*)(g_K16 + (size_t)(row + 8) * HS + coff) =
                    pack_h2(acc[f][g][2], acc[f][g][3]);
            } else {                    // V: single fp16
                *(unsigned*)(g_V16 + (size_t)row * HS + coff) =
                    pack_h2(acc[f][g][0], acc[f][g][1]);
                *(unsigned*)(g_V16 + (size_t)(row + 8) * HS + coff) =
                    pack_h2(acc[f][g][2], acc[f][g][3]);
            }
        }
    }
}

// ---------------------------------------------------------------------------
// Kernel 2: causal flash attention. QK^T = Qhi*K + Qlo*K (2-pass fp16,
// K single fp16 -> 2^-12 rounding), PV fp16 single-pass. exp2 domain.
// K/V double-buffered, ONE sync per tile. Split-K <=9 tiles, grid 296 =
// one wave at 2 CTAs/SM. Fused last-CTA merge. Heavy-first.
// ---------------------------------------------------------------------------
#define FST 72
#define F_TILE (64 * FST)
#define F_TILE_B (F_TILE * 2)            // 9216
#define KV_STAGE_B (2 * F_TILE_B)        // K16, V16 = 18432
#define F_SMEM_BYTES (2 * F_TILE_B + 2 * KV_STAGE_B)   // 55296

__global__ __launch_bounds__(128, 2) void flash_kernel(float* __restrict__ out)
{
    extern __shared__ __half fsh[];
    __half* sQh = fsh;
    __half* sQl = sQh + F_TILE;
    __shared__ unsigned s_flag;

    // chunk -> (qblk, part, ns), ns = ceil((q+1)/9), heavy-first
    const int i = blockIdx.x;       // 0..73
    int qblk, part, ns;
    if (i < 20)      { qblk = 31 - (i >> 2); part = i & 3; ns = 4; }
    else if (i < 47) { int t = i - 20; qblk = 26 - t / 3; part = t % 3; ns = 3; }
    else if (i < 65) { int t = i - 47; qblk = 17 - (t >> 1); part = t & 1; ns = 2; }
    else             { int t = i - 65; qblk = 8 - t; part = 0; ns = 1; }
    const int b  = blockIdx.y;
    const int nt = qblk + 1;
    const int jb = part * nt / ns;
    const int je = (part + 1) * nt / ns;

    const int tid  = threadIdx.x;
    const int w    = tid >> 5;
    const int lane = tid & 31;
    const size_t base = (size_t)b * SEQ * HS;

    const unsigned sbase = smem_u32(fsh);
    const unsigned kv0   = sbase + 2 * F_TILE_B;

#pragma unroll
    for (int k = tid; k < 64 * 8; k += 128) {
        const int row = k >> 3, u = k & 7;
        const size_t gi = base + (size_t)(jb * 64 + row) * HS + u * 8;
        const unsigned d = kv0 + (unsigned)(row * FST + u * 8) * 2;
        CP_ASYNC16(d,            g_K16 + gi);
        CP_ASYNC16(d + F_TILE_B, g_V16 + gi);
    }
    CP_COMMIT();

#pragma unroll
    for (int k = tid; k < 64 * 8; k += 128) {
        const int row = k >> 3, u = k & 7;
        const size_t gi = base + (size_t)(qblk * 64 + row) * HS + u * 8;
        *(uint4*)(sQh + row * FST + u * 8) = *(const uint4*)(g_Qhi + gi);
        *(uint4*)(sQl + row * FST + u * 8) = *(const uint4*)(g_Qlo + gi);
    }
    __syncthreads();

    const unsigned sQh_u = sbase, sQl_u = sbase + F_TILE_B;
    unsigned qh[4][4], ql[4][4];
    {
        const int ar = w * 16 + (lane & 15);
        const int ac = (lane >> 4) * 8;
#pragma unroll
        for (int ks = 0; ks < 4; ks++) {
            const unsigned off = (ar * FST + ks * 16 + ac) * 2;
            ldm_x4(sQh_u + off, qh[ks]);
            ldm_x4(sQl_u + off, ql[ks]);
        }
    }

    float o[8][4];
#pragma unroll
    for (int nf = 0; nf < 8; nf++)
#pragma unroll
        for (int e = 0; e < 4; e++) o[nf][e] = 0.f;
    float mA = -1e30f, mB = -1e30f, lA = 0.f, lB = 0.f;

    const int b_sub = lane >> 3;
    const int kb_row = (b_sub >> 1) * 8 + (lane & 7);
    const int kb_col = (b_sub & 1) * 8;
    const int vb_row = (b_sub & 1) * 8 + (lane & 7);
    const int vb_col = (b_sub >> 1) * 8;

    for (int j = jb; j < je; j++) {
        const int cur = (j - jb) & 1;

        CP_WAIT0();
        __syncthreads();

        if (j + 1 < je) {
            const unsigned nb = kv0 + (cur ^ 1) * KV_STAGE_B;
#pragma unroll
            for (int k = tid; k < 64 * 8; k += 128) {
                const int row = k >> 3, u = k & 7;
                const size_t gi = base + (size_t)((j + 1) * 64 + row) * HS + u * 8;
                const unsigned d = nb + (unsigned)(row * FST + u * 8) * 2;
                CP_ASYNC16(d,            g_K16 + gi);
                CP_ASYNC16(d + F_TILE_B, g_V16 + gi);
            }
            CP_COMMIT();
        }

        const unsigned sK_u = kv0 + cur * KV_STAGE_B;
        const unsigned sV_u = sK_u + F_TILE_B;

        float s[8][4];
#pragma unroll
        for (int nf = 0; nf < 8; nf++)
#pragma unroll
            for (int e = 0; e < 4; e++) s[nf][e] = 0.f;

#pragma unroll
        for (int ks = 0; ks < 4; ks++) {
            unsigned kh[8][2];
#pragma unroll
            for (int np = 0; np < 4; np++) {
                const unsigned off = ((np * 16 + kb_row) * FST + ks * 16 + kb_col) * 2;
                unsigned t[4];
                ldm_x4(sK_u + off, t);
                kh[np * 2][0] = t[0]; kh[np * 2][1] = t[1];
                kh[np * 2 + 1][0] = t[2]; kh[np * 2 + 1][1] = t[3];
            }
#pragma unroll
            for (int nf = 0; nf < 8; nf++) {
                mma_f16(s[nf], qh[ks], kh[nf]);
                mma_f16(s[nf], ql[ks], kh[nf]);
            }
        }

        // Hoisted V-fragment loads (overlap softmax MUFU chain)
        unsigned vh[4][8][2];
#pragma unroll
        for (int ks = 0; ks < 4; ks++)
#pragma unroll
            for (int hp = 0; hp < 4; hp++) {
                const unsigned off = ((ks * 16 + vb_row) * FST + hp * 16 + vb_col) * 2;
                unsigned t[4];
                ldm_x4t(sV_u + off, t);
                vh[ks][hp * 2][0] = t[0]; vh[ks][hp * 2][1] = t[1];
                vh[ks][hp * 2 + 1][0] = t[2]; vh[ks][hp * 2 + 1][1] = t[3];
            }

        if (j == qblk) {
            const int rA = w * 16 + (lane >> 2);
            const int c0 = (lane & 3) * 2;
#pragma unroll
            for (int nf = 0; nf < 8; nf++) {
                const int c = nf * 8 + c0;
                if (c > rA)         s[nf][0] = -1e30f;
                if (c + 1 > rA)     s[nf][1] = -1e30f;
                if (c > rA + 8)     s[nf][2] = -1e30f;
                if (c + 1 > rA + 8) s[nf][3] = -1e30f;
            }
        }

        float tmA = -1e30f, tmB = -1e30f;
#pragma unroll
        for (int nf = 0; nf < 8; nf++) {
            tmA = fmaxf(tmA, fmaxf(s[nf][0], s[nf][1]));
            tmB = fmaxf(tmB, fmaxf(s[nf][2], s[nf][3]));
        }
#pragma unroll
        for (int off = 1; off < 4; off <<= 1) {
            tmA = fmaxf(tmA, __shfl_xor_sync(0xffffffffu, tmA, off));
            tmB = fmaxf(tmB, __shfl_xor_sync(0xffffffffu, tmB, off));
        }
        const float mnA = fmaxf(mA, tmA), mnB = fmaxf(mB, tmB);
        const float aA = ex2(mA - mnA), aB = ex2(mB - mnB);
        mA = mnA; mB = mnB;

        float sumA = 0.f, sumB = 0.f;
#pragma unroll
        for (int nf = 0; nf < 8; nf++) {
            s[nf][0] = ex2(s[nf][0] - mnA); sumA += s[nf][0];
            s[nf][1] = ex2(s[nf][1] - mnA); sumA += s[nf][1];
            s[nf][2] = ex2(s[nf][2] - mnB); sumB += s[nf][2];
            s[nf][3] = ex2(s[nf][3] - mnB); sumB += s[nf][3];
        }
#pragma unroll
        for (int off = 1; off < 4; off <<= 1) {
            sumA += __shfl_xor_sync(0xffffffffu, sumA, off);
            sumB += __shfl_xor_sync(0xffffffffu, sumB, off);
        }
        lA = lA * aA + sumA;
        lB = lB * aB + sumB;
#pragma unroll
        for (int nf = 0; nf < 8; nf++) {
            o[nf][0] *= aA; o[nf][1] *= aA;
            o[nf][2] *= aB; o[nf][3] *= aB;
        }

#pragma unroll
        for (int ks = 0; ks < 4; ks++) {
            unsigned ap[4];
            ap[0] = pack_h2(s[2 * ks][0],     s[2 * ks][1]);
            ap[1] = pack_h2(s[2 * ks][2],     s[2 * ks][3]);
            ap[2] = pack_h2(s[2 * ks + 1][0], s[2 * ks + 1][1]);
            ap[3] = pack_h2(s[2 * ks + 1][2], s[2 * ks + 1][3]);
#pragma unroll
            for (int nf = 0; nf < 8; nf++)
                mma_f16(o[nf], ap, vh[ks][nf]);
        }
    }

    const int rA = qblk * 64 + w * 16 + (lane >> 2);
    const size_t grA = (size_t)b * SEQ + rA;
    const size_t grB = grA + 8;
    const int c0 = (lane & 3) * 2;

    if (ns == 1) {
        const float invA = 1.f / lA, invB = 1.f / lB;
#pragma unroll
        for (int nf = 0; nf < 8; nf++) {
            const int c = nf * 8 + c0;
            *(float2*)(out + grA * HS + c) =
                make_float2(o[nf][0] * invA, o[nf][1] * invA);
            *(float2*)(out + grB * HS + c) =
                make_float2(o[nf][2] * invB, o[nf][3] * invB);
        }
        return;
    }

#pragma unroll
    for (int nf = 0; nf < 8; nf++) {
        const int c = nf * 8 + c0;
        *(float2*)(&g_Opart[part][grA * HS + c]) = make_float2(o[nf][0], o[nf][1]);
        *(float2*)(&g_Opart[part][grB * HS + c]) = make_float2(o[nf][2], o[nf][3]);
    }
    if ((lane & 3) == 0) {
        g_mpart[part][grA] = mA; g_lpart[part][grA] = lA;
        g_mpart[part][grB] = mB; g_lpart[part][grB] = lB;
    }

    __threadfence();
    if (tid == 0) {
        const unsigned old = atomicAdd(&g_cnt[b * 32 + qblk], 1);
        s_flag = (old == (unsigned)(ns - 1)) ? 1u : 0u;
    }
    __syncthreads();
    if (s_flag) {
        __threadfence();
#pragma unroll
        for (int it = 0; it < 8; it++) {
            const int slot = tid + it * 128;
            const int rl = slot >> 4, u = slot & 15;
            const size_t gr = (size_t)b * SEQ + qblk * 64 + rl;
            float m = -1e30f;
            for (int p = 0; p < ns; p++) m = fmaxf(m, g_mpart[p][gr]);
            float ap[4], den = 0.f;
            for (int p = 0; p < ns; p++) {
                ap[p] = ex2(g_mpart[p][gr] - m);
                den += g_lpart[p][gr] * ap[p];
            }
            const float inv = 1.f / den;
            float4 acc = make_float4(0.f, 0.f, 0.f, 0.f);
            for (int p = 0; p < ns; p++) {
                float4 v = ((const float4*)(g_Opart[p] + gr * HS))[u];
                acc.x += v.x * ap[p]; acc.y += v.y * ap[p];
                acc.z += v.z * ap[p]; acc.w += v.w * ap[p];
            }
            acc.x *= inv; acc.y *= inv; acc.z *= inv; acc.w *= inv;
            ((float4*)(out + gr * HS))[u] = acc;
        }
        __syncthreads();
        if (tid == 0) g_cnt[b * 32 + qblk] = 0;
    }
}

// ---------------------------------------------------------------------------

extern "C" void kernel_launch(void* const* d_in, const int* in_sizes, int n_in,
                              void* d_out, int out_size)
{
    const float* x  = (const float*)d_in[0];
    const float* Wq = (const float*)d_in[1];
    const float* Wk = (const float*)d_in[2];
    const float* Wv = (const float*)d_in[3];
    float* out      = (float*)d_out;
    (void)in_sizes; (void)n_in; (void)out_size;

    cudaFuncSetAttribute(qkv_gemm_kernel,
                         cudaFuncAttributeMaxDynamicSharedMemorySize, G_SMEM_BYTES);
    cudaFuncSetAttribute(flash_kernel,
                         cudaFuncAttributeMaxDynamicSharedMemorySize, F_SMEM_BYTES);

    wconv_kernel<<<(NCOMB * EMB / 4 + 255) / 256, 256>>>(Wq, Wk, Wv);
    qkv_gemm_kernel<<<MROWS / 64, 256, G_SMEM_BYTES>>>(x);
    flash_kernel<<<dim3(74, BATCH), 128, F_SMEM_BYTES>>>(out);
}

// round 15
// speedup vs baseline: 1.4711x; 1.2600x over previous
#include <cuda_runtime.h>
#include <cuda_bf16.h>
#include <cuda_fp16.h>
#include <cstdint>

#define BATCH 4
#define SEQ   2048
#define EMB   1024
#define HS    64
#define MROWS (BATCH * SEQ)     // 8192
#define NCOMB 192               // Wq | Wk | Wv stacked

// Q pre-scale: HS^-0.5 * log2(e)  (softmax done in exp2 domain)
#define QSCALE 0.180336880111f

// ---------------------------------------------------------------------------
// Device scratch (no allocations allowed)
// ---------------------------------------------------------------------------
__device__ __half g_W16[NCOMB * EMB];  // single fp16 W (combined)
__device__ __half g_Qhi[MROWS * HS];   // fp16 hi/lo, pre-scaled by QSCALE
__device__ __half g_Qlo[MROWS * HS];
__device__ __half g_K16[MROWS * HS];   // single-pass fp16 K
__device__ __half g_V16[MROWS * HS];   // single-pass fp16 V
__device__ float g_Opart[4][MROWS * HS];
__device__ float g_mpart[4][MROWS];
__device__ float g_lpart[4][MROWS];
__device__ unsigned g_cnt[BATCH * 32];        // zero-init; self-resetting

// ---------------------------------------------------------------------------
// Helpers
// ---------------------------------------------------------------------------
static __device__ __forceinline__ unsigned smem_u32(const void* p) {
    unsigned a;
    asm("{ .reg .u64 t; cvta.to.shared.u64 t, %1; cvt.u32.u64 %0, t; }"
        : "=r"(a) : "l"(p));
    return a;
}
static __device__ __forceinline__ void ldm_x4(unsigned addr, unsigned r[4]) {
    asm volatile("ldmatrix.sync.aligned.m8n8.x4.shared.b16 {%0,%1,%2,%3}, [%4];"
                 : "=r"(r[0]), "=r"(r[1]), "=r"(r[2]), "=r"(r[3]) : "r"(addr));
}
static __device__ __forceinline__ void ldm_x4t(unsigned addr, unsigned r[4]) {
    asm volatile("ldmatrix.sync.aligned.m8n8.x4.trans.shared.b16 {%0,%1,%2,%3}, [%4];"
                 : "=r"(r[0]), "=r"(r[1]), "=r"(r[2]), "=r"(r[3]) : "r"(addr));
}
static __device__ __forceinline__ void mma_f16(float c[4], const unsigned a[4],
                                               const unsigned b[2]) {
    asm volatile(
        "mma.sync.aligned.m16n8k16.row.col.f32.f16.f16.f32 "
        "{%0,%1,%2,%3}, {%4,%5,%6,%7}, {%8,%9}, {%0,%1,%2,%3};"
        : "+f"(c[0]), "+f"(c[1]), "+f"(c[2]), "+f"(c[3])
        : "r"(a[0]), "r"(a[1]), "r"(a[2]), "r"(a[3]), "r"(b[0]), "r"(b[1]));
}
static __device__ __forceinline__ void split_hl_f16(float v0, float v1,
                                                    unsigned& hi, unsigned& lo) {
    __half h0 = __float2half(v0), h1 = __float2half(v1);
    __half2 h = __halves2half2(h0, h1);
    __half2 l = __halves2half2(__float2half(v0 - __half2float(h0)),
                               __float2half(v1 - __half2float(h1)));
    hi = reinterpret_cast<unsigned&>(h);
    lo = reinterpret_cast<unsigned&>(l);
}
static __device__ __forceinline__ unsigned pack_h2(float lo, float hi) {
    unsigned r;
    asm("cvt.rn.f16x2.f32 %0, %1, %2;" : "=r"(r) : "f"(hi), "f"(lo));
    return r;
}
static __device__ __forceinline__ float ex2(float x) {
    float y;
    asm("ex2.approx.ftz.f32 %0, %1;" : "=f"(y) : "f"(x));
    return y;
}
#define CP_ASYNC16(dst, src) \
    asm volatile("cp.async.cg.shared.global [%0], [%1], 16;" :: "r"(dst), "l"(src))
#define CP_COMMIT() asm volatile("cp.async.commit_group;")
#define CP_WAIT0()  asm volatile("cp.async.wait_group 0;")

// ---------------------------------------------------------------------------
// Kernel 0: W -> single fp16
// ---------------------------------------------------------------------------
__global__ __launch_bounds__(256) void wconv_kernel(
    const float* __restrict__ Wq, const float* __restrict__ Wk,
    const float* __restrict__ Wv)
{
    const int i = blockIdx.x * 256 + threadIdx.x;
    if (i >= NCOMB * EMB / 4) return;
    const int e = i * 4, row = e >> 10, col = e & 1023;
    const float* src = (row < 64)  ? (Wq + (size_t)row * EMB)
                     : (row < 128) ? (Wk + (size_t)(row - 64) * EMB)
                                   : (Wv + (size_t)(row - 128) * EMB);
    float4 v = *(const float4*)(src + col);
    uint2 p;
    p.x = pack_h2(v.x, v.y);
    p.y = pack_h2(v.z, v.w);
    ((uint2*)g_W16)[i] = p;
}

// ---------------------------------------------------------------------------
// Kernel 1: combined QKV GEMM, mma.sync fp16: x hi/lo (2-pass) x W single.
// BK=64, A+B double-buffered, ONE __syncthreads per chunk. smem 92KB ->
// 2 CTAs/SM. CTA 64x192, 256 thr, grid 128.
// ---------------------------------------------------------------------------
#define AST 72
#define A_STAGE_B 18432              // hi (9216) + lo (9216) per stage
#define B_OFF     36864
#define B_BUF_BYTES 27648            // single fp16, one stage (192*72*2)
#define G_SMEM_BYTES (B_OFF + 2 * B_BUF_BYTES)   // 92160

__global__ __launch_bounds__(256, 2) void qkv_gemm_kernel(const float* __restrict__ x)
{
    extern __shared__ char smc[];
    const unsigned sbase = smem_u32(smc);
    const int tid  = threadIdx.x;
    const int wid  = tid >> 5;
    const int lane = tid & 31;
    const int wm   = wid & 1;
    const int wn   = wid >> 1;
    const int m0   = blockIdx.x * 64;

    float acc[2][6][4];
#pragma unroll
    for (int f = 0; f < 2; f++)
#pragma unroll
        for (int g = 0; g < 6; g++)
#pragma unroll
            for (int e = 0; e < 4; e++) acc[f][g][e] = 0.f;

    const int a_row = wm * 32 + (lane & 15);
    const int a_col = (lane >> 4) * 8;
    const int b_sub = lane >> 3;
    const int b_row = (b_sub >> 1) * 8 + (lane & 7);
    const int b_col = (b_sub & 1) * 8;

    // ---- prologue: A(0) -> smem stage 0; av <- A(1); cp.async B(0) ----
#pragma unroll
    for (int it = 0; it < 4; it++) {
        const int i = tid + it * 256;
        const int row = i >> 4, u = i & 15;
        float4 v = *(const float4*)(x + (size_t)(m0 + row) * EMB + u * 4);
        uint2 hp, lp;
        split_hl_f16(v.x, v.y, hp.x, lp.x);
        split_hl_f16(v.z, v.w, hp.y, lp.y);
        *(uint2*)(smc + (row * AST + u * 4) * 2)        = hp;
        *(uint2*)(smc + 9216 + (row * AST + u * 4) * 2) = lp;
    }
    float4 av[4];
#pragma unroll
    for (int it = 0; it < 4; it++) {
        const int i = tid + it * 256;
        const int row = i >> 4, u = i & 15;
        av[it] = *(const float4*)(x + (size_t)(m0 + row) * EMB + 64 + u * 4);
    }
#pragma unroll
    for (int i = tid; i < 192 * 8; i += 256) {
        const int row = i >> 3, u = i & 7;
        const unsigned d = sbase + B_OFF + (unsigned)(row * AST + u * 8) * 2;
        CP_ASYNC16(d, g_W16 + (size_t)row * EMB + u * 8);
    }
    CP_COMMIT();

    for (int c = 0; c < 16; c++) {
        CP_WAIT0();            // drain B(c)
        __syncthreads();       // publish B(c) + A(c) stores; frees (c+1)&1 bufs

        if (c + 1 < 16) {
            char* abase = smc + ((c + 1) & 1) * A_STAGE_B;
#pragma unroll
            for (int it = 0; it < 4; it++) {
                const int i = tid + it * 256;
                const int row = i >> 4, u = i & 15;
                uint2 hp, lp;
                split_hl_f16(av[it].x, av[it].y, hp.x, lp.x);
                split_hl_f16(av[it].z, av[it].w, hp.y, lp.y);
                *(uint2*)(abase + (row * AST + u * 4) * 2)        = hp;
                *(uint2*)(abase + 9216 + (row * AST + u * 4) * 2) = lp;
            }
            if (c + 2 < 16) {
                const int c2 = (c + 2) * 64;
#pragma unroll
                for (int it = 0; it < 4; it++) {
                    const int i = tid + it * 256;
                    const int row = i >> 4, u = i & 15;
                    av[it] = *(const float4*)(x + (size_t)(m0 + row) * EMB + c2 + u * 4);
                }
            }
            const int c1 = (c + 1) * 64;
            const unsigned bb = sbase + B_OFF + ((c + 1) & 1) * B_BUF_BYTES;
#pragma unroll
            for (int i = tid; i < 192 * 8; i += 256) {
                const int row = i >> 3, u = i & 7;
                const unsigned d = bb + (unsigned)(row * AST + u * 8) * 2;
                CP_ASYNC16(d, g_W16 + (size_t)row * EMB + c1 + u * 8);
            }
            CP_COMMIT();
        }

        // compute chunk c (fp16 2-pass)
        const unsigned sAhi_u = sbase + (c & 1) * A_STAGE_B;
        const unsigned sAlo_u = sAhi_u + 9216;
        const unsigned sB_u   = sbase + B_OFF + (c & 1) * B_BUF_BYTES;

#pragma unroll
        for (int ks = 0; ks < 4; ks++) {
            unsigned ah[2][4], al[2][4], bh[6][2];
#pragma unroll
            for (int f = 0; f < 2; f++) {
                const unsigned off = ((a_row + f * 16) * AST + a_col + ks * 16) * 2;
                ldm_x4(sAhi_u + off, ah[f]);
                ldm_x4(sAlo_u + off, al[f]);
            }
#pragma unroll
            for (int p = 0; p < 3; p++) {
                const unsigned off =
                    ((wn * 48 + p * 16 + b_row) * AST + b_col + ks * 16) * 2;
                unsigned t[4];
                ldm_x4(sB_u + off, t);
                bh[p * 2][0] = t[0]; bh[p * 2][1] = t[1];
                bh[p * 2 + 1][0] = t[2]; bh[p * 2 + 1][1] = t[3];
            }
#pragma unroll
            for (int f = 0; f < 2; f++)
#pragma unroll
                for (int g = 0; g < 6; g++) {
                    mma_f16(acc[f][g], ah[f], bh[g]);
                    mma_f16(acc[f][g], al[f], bh[g]);
                }
        }
    }

    // Epilogue: Q fp16 hi/lo (pre-scaled), K fp16, V fp16
#pragma unroll
    for (int g = 0; g < 6; g++) {
        const int nblk = wn * 48 + g * 8;
        const int coff = (nblk & 63) + (lane & 3) * 2;
#pragma unroll
        for (int f = 0; f < 2; f++) {
            const int row = m0 + wm * 32 + f * 16 + (lane >> 2);
            if (nblk < 64) {
                unsigned h0, l0, h1, l1;
                split_hl_f16(acc[f][g][0] * QSCALE, acc[f][g][1] * QSCALE, h0, l0);
                split_hl_f16(acc[f][g][2] * QSCALE, acc[f][g][3] * QSCALE, h1, l1);
                *(unsigned*)(g_Qhi + (size_t)row * HS + coff)       = h0;
                *(unsigned*)(g_Qlo + (size_t)row * HS + coff)       = l0;
                *(unsigned*)(g_Qhi + (size_t)(row + 8) * HS + coff) = h1;
                *(unsigned*)(g_Qlo + (size_t)(row + 8) * HS + coff) = l1;
            } else if (nblk < 128) {
                *(unsigned*)(g_K16 + (size_t)row * HS + coff) =
                    pack_h2(acc[f][g][0], acc[f][g][1]);
                *(unsigned*)(g_K16 + (size_t)(row + 8) * HS + coff) =
                    pack_h2(acc[f][g][2], acc[f][g][3]);
            } else {
                *(unsigned*)(g_V16 + (size_t)row * HS + coff) =
                    pack_h2(acc[f][g][0], acc[f][g][1]);
                *(unsigned*)(g_V16 + (size_t)(row + 8) * HS + coff) =
                    pack_h2(acc[f][g][2], acc[f][g][3]);
            }
        }
    }
}

// ---------------------------------------------------------------------------
// Kernel 2: causal flash attention (R14 config, unchanged).
// QK^T = Qhi*K + Qlo*K (2-pass fp16), PV fp16 single-pass. exp2 domain.
// K/V double-buffered, ONE sync per tile. Split-K <=9 tiles, grid 296 =
// one wave at 2 CTAs/SM. Fused last-CTA merge. Heavy-first.
// ---------------------------------------------------------------------------
#define FST 72
#define F_TILE (64 * FST)
#define F_TILE_B (F_TILE * 2)            // 9216
#define KV_STAGE_B (2 * F_TILE_B)        // K16, V16 = 18432
#define F_SMEM_BYTES (2 * F_TILE_B + 2 * KV_STAGE_B)   // 55296

__global__ __launch_bounds__(128, 2) void flash_kernel(float* __restrict__ out)
{
    extern __shared__ __half fsh[];
    __half* sQh = fsh;
    __half* sQl = sQh + F_TILE;
    __shared__ unsigned s_flag;

    // chunk -> (qblk, part, ns), ns = ceil((q+1)/9), heavy-first
    const int i = blockIdx.x;       // 0..73
    int qblk, part, ns;
    if (i < 20)      { qblk = 31 - (i >> 2); part = i & 3; ns = 4; }
    else if (i < 47) { int t = i - 20; qblk = 26 - t / 3; part = t % 3; ns = 3; }
    else if (i < 65) { int t = i - 47; qblk = 17 - (t >> 1); part = t & 1; ns = 2; }
    else             { int t = i - 65; qblk = 8 - t; part = 0; ns = 1; }
    const int b  = blockIdx.y;
    const int nt = qblk + 1;
    const int jb = part * nt / ns;
    const int je = (part + 1) * nt / ns;

    const int tid  = threadIdx.x;
    const int w    = tid >> 5;
    const int lane = tid & 31;
    const size_t base = (size_t)b * SEQ * HS;

    const unsigned sbase = smem_u32(fsh);
    const unsigned kv0   = sbase + 2 * F_TILE_B;

#pragma unroll
    for (int k = tid; k < 64 * 8; k += 128) {
        const int row = k >> 3, u = k & 7;
        const size_t gi = base + (size_t)(jb * 64 + row) * HS + u * 8;
        const unsigned d = kv0 + (unsigned)(row * FST + u * 8) * 2;
        CP_ASYNC16(d,            g_K16 + gi);
        CP_ASYNC16(d + F_TILE_B, g_V16 + gi);
    }
    CP_COMMIT();

#pragma unroll
    for (int k = tid; k < 64 * 8; k += 128) {
        const int row = k >> 3, u = k & 7;
        const size_t gi = base + (size_t)(qblk * 64 + row) * HS + u * 8;
        *(uint4*)(sQh + row * FST + u * 8) = *(const uint4*)(g_Qhi + gi);
        *(uint4*)(sQl + row * FST + u * 8) = *(const uint4*)(g_Qlo + gi);
    }
    __syncthreads();

    const unsigned sQh_u = sbase, sQl_u = sbase + F_TILE_B;
    unsigned qh[4][4], ql[4][4];
    {
        const int ar = w * 16 + (lane & 15);
        const int ac = (lane >> 4) * 8;
#pragma unroll
        for (int ks = 0; ks < 4; ks++) {
            const unsigned off = (ar * FST + ks * 16 + ac) * 2;
            ldm_x4(sQh_u + off, qh[ks]);
            ldm_x4(sQl_u + off, ql[ks]);
        }
    }

    float o[8][4];
#pragma unroll
    for (int nf = 0; nf < 8; nf++)
#pragma unroll
        for (int e = 0; e < 4; e++) o[nf][e] = 0.f;
    float mA = -1e30f, mB = -1e30f, lA = 0.f, lB = 0.f;

    const int b_sub = lane >> 3;
    const int kb_row = (b_sub >> 1) * 8 + (lane & 7);
    const int kb_col = (b_sub & 1) * 8;
    const int vb_row = (b_sub & 1) * 8 + (lane & 7);
    const int vb_col = (b_sub >> 1) * 8;

    for (int j = jb; j < je; j++) {
        const int cur = (j - jb) & 1;

        CP_WAIT0();
        __syncthreads();

        if (j + 1 < je) {
            const unsigned nb = kv0 + (cur ^ 1) * KV_STAGE_B;
#pragma unroll
            for (int k = tid; k < 64 * 8; k += 128) {
                const int row = k >> 3, u = k & 7;
                const size_t gi = base + (size_t)((j + 1) * 64 + row) * HS + u * 8;
                const unsigned d = nb + (unsigned)(row * FST + u * 8) * 2;
                CP_ASYNC16(d,            g_K16 + gi);
                CP_ASYNC16(d + F_TILE_B, g_V16 + gi);
            }
            CP_COMMIT();
        }

        const unsigned sK_u = kv0 + cur * KV_STAGE_B;
        const unsigned sV_u = sK_u + F_TILE_B;

        float s[8][4];
#pragma unroll
        for (int nf = 0; nf < 8; nf++)
#pragma unroll
            for (int e = 0; e < 4; e++) s[nf][e] = 0.f;

#pragma unroll
        for (int ks = 0; ks < 4; ks++) {
            unsigned kh[8][2];
#pragma unroll
            for (int np = 0; np < 4; np++) {
                const unsigned off = ((np * 16 + kb_row) * FST + ks * 16 + kb_col) * 2;
                unsigned t[4];
                ldm_x4(sK_u + off, t);
                kh[np * 2][0] = t[0]; kh[np * 2][1] = t[1];
                kh[np * 2 + 1][0] = t[2]; kh[np * 2 + 1][1] = t[3];
            }
#pragma unroll
            for (int nf = 0; nf < 8; nf++) {
                mma_f16(s[nf], qh[ks], kh[nf]);
                mma_f16(s[nf], ql[ks], kh[nf]);
            }
        }

        // Hoisted V-fragment loads (overlap softmax MUFU chain)
        unsigned vh[4][8][2];
#pragma unroll
        for (int ks = 0; ks < 4; ks++)
#pragma unroll
            for (int hp = 0; hp < 4; hp++) {
                const unsigned off = ((ks * 16 + vb_row) * FST + hp * 16 + vb_col) * 2;
                unsigned t[4];
                ldm_x4t(sV_u + off, t);
                vh[ks][hp * 2][0] = t[0]; vh[ks][hp * 2][1] = t[1];
                vh[ks][hp * 2 + 1][0] = t[2]; vh[ks][hp * 2 + 1][1] = t[3];
            }

        if (j == qblk) {
            const int rA = w * 16 + (lane >> 2);
            const int c0 = (lane & 3) * 2;
#pragma unroll
            for (int nf = 0; nf < 8; nf++) {
                const int c = nf * 8 + c0;
                if (c > rA)         s[nf][0] = -1e30f;
                if (c + 1 > rA)     s[nf][1] = -1e30f;
                if (c > rA + 8)     s[nf][2] = -1e30f;
                if (c + 1 > rA + 8) s[nf][3] = -1e30f;
            }
        }

        float tmA = -1e30f, tmB = -1e30f;
#pragma unroll
        for (int nf = 0; nf < 8; nf++) {
            tmA = fmaxf(tmA, fmaxf(s[nf][0], s[nf][1]));
            tmB = fmaxf(tmB, fmaxf(s[nf][2], s[nf][3]));
        }
#pragma unroll
        for (int off = 1; off < 4; off <<= 1) {
            tmA = fmaxf(tmA, __shfl_xor_sync(0xffffffffu, tmA, off));
            tmB = fmaxf(tmB, __shfl_xor_sync(0xffffffffu, tmB, off));
        }
        const float mnA = fmaxf(mA, tmA), mnB = fmaxf(mB, tmB);
        const float aA = ex2(mA - mnA), aB = ex2(mB - mnB);
        mA = mnA; mB = mnB;

        float sumA = 0.f, sumB = 0.f;
#pragma unroll
        for (int nf = 0; nf < 8; nf++) {
            s[nf][0] = ex2(s[nf][0] - mnA); sumA += s[nf][0];
            s[nf][1] = ex2(s[nf][1] - mnA); sumA += s[nf][1];
            s[nf][2] = ex2(s[nf][2] - mnB); sumB += s[nf][2];
            s[nf][3] = ex2(s[nf][3] - mnB); sumB += s[nf][3];
        }
#pragma unroll
        for (int off = 1; off < 4; off <<= 1) {
            sumA += __shfl_xor_sync(0xffffffffu, sumA, off);
            sumB += __shfl_xor_sync(0xffffffffu, sumB, off);
        }
        lA = lA * aA + sumA;
        lB = lB * aB + sumB;
#pragma unroll
        for (int nf = 0; nf < 8; nf++) {
            o[nf][0] *= aA; o[nf][1] *= aA;
            o[nf][2] *= aB; o[nf][3] *= aB;
        }

#pragma unroll
        for (int ks = 0; ks < 4; ks++) {
            unsigned ap[4];
            ap[0] = pack_h2(s[2 * ks][0],     s[2 * ks][1]);
            ap[1] = pack_h2(s[2 * ks][2],     s[2 * ks][3]);
            ap[2] = pack_h2(s[2 * ks + 1][0], s[2 * ks + 1][1]);
            ap[3] = pack_h2(s[2 * ks + 1][2], s[2 * ks + 1][3]);
#pragma unroll
            for (int nf = 0; nf < 8; nf++)
                mma_f16(o[nf], ap, vh[ks][nf]);
        }
    }

    const int rA = qblk * 64 + w * 16 + (lane >> 2);
    const size_t grA = (size_t)b * SEQ + rA;
    const size_t grB = grA + 8;
    const int c0 = (lane & 3) * 2;

    if (ns == 1) {
        const float invA = 1.f / lA, invB = 1.f / lB;
#pragma unroll
        for (int nf = 0; nf < 8; nf++) {
            const int c = nf * 8 + c0;
            *(float2*)(out + grA * HS + c) =
                make_float2(o[nf][0] * invA, o[nf][1] * invA);
            *(float2*)(out + grB * HS + c) =
                make_float2(o[nf][2] * invB, o[nf][3] * invB);
        }
        return;
    }

#pragma unroll
    for (int nf = 0; nf < 8; nf++) {
        const int c = nf * 8 + c0;
        *(float2*)(&g_Opart[part][grA * HS + c]) = make_float2(o[nf][0], o[nf][1]);
        *(float2*)(&g_Opart[part][grB * HS + c]) = make_float2(o[nf][2], o[nf][3]);
    }
    if ((lane & 3) == 0) {
        g_mpart[part][grA] = mA; g_lpart[part][grA] = lA;
        g_mpart[part][grB] = mB; g_lpart[part][grB] = lB;
    }

    __threadfence();
    if (tid == 0) {
        const unsigned old = atomicAdd(&g_cnt[b * 32 + qblk], 1);
        s_flag = (old == (unsigned)(ns - 1)) ? 1u : 0u;
    }
    __syncthreads();
    if (s_flag) {
        __threadfence();
#pragma unroll
        for (int it = 0; it < 8; it++) {
            const int slot = tid + it * 128;
            const int rl = slot >> 4, u = slot & 15;
            const size_t gr = (size_t)b * SEQ + qblk * 64 + rl;
            float m = -1e30f;
            for (int p = 0; p < ns; p++) m = fmaxf(m, g_mpart[p][gr]);
            float ap[4], den = 0.f;
            for (int p = 0; p < ns; p++) {
                ap[p] = ex2(g_mpart[p][gr] - m);
                den += g_lpart[p][gr] * ap[p];
            }
            const float inv = 1.f / den;
            float4 acc = make_float4(0.f, 0.f, 0.f, 0.f);
            for (int p = 0; p < ns; p++) {
                float4 v = ((const float4*)(g_Opart[p] + gr * HS))[u];
                acc.x += v.x * ap[p]; acc.y += v.y * ap[p];
                acc.z += v.z * ap[p]; acc.w += v.w * ap[p];
            }
            acc.x *= inv; acc.y *= inv; acc.z *= inv; acc.w *= inv;
            ((float4*)(out + gr * HS))[u] = acc;
        }
        __syncthreads();
        if (tid == 0) g_cnt[b * 32 + qblk] = 0;
    }
}

// ---------------------------------------------------------------------------

extern "C" void kernel_launch(void* const* d_in, const int* in_sizes, int n_in,
                              void* d_out, int out_size)
{
    const float* x  = (const float*)d_in[0];
    const float* Wq = (const float*)d_in[1];
    const float* Wk = (const float*)d_in[2];
    const float* Wv = (const float*)d_in[3];
    float* out      = (float*)d_out;
    (void)in_sizes; (void)n_in; (void)out_size;

    cudaFuncSetAttribute(qkv_gemm_kernel,
                         cudaFuncAttributeMaxDynamicSharedMemorySize, G_SMEM_BYTES);
    cudaFuncSetAttribute(flash_kernel,
                         cudaFuncAttributeMaxDynamicSharedMemorySize, F_SMEM_BYTES);

    wconv_kernel<<<(NCOMB * EMB / 4 + 255) / 256, 256>>>(Wq, Wk, Wv);
    qkv_gemm_kernel<<<MROWS / 64, 256, G_SMEM_BYTES>>>(x);
    flash_kernel<<<dim3(74, BATCH), 128, F_SMEM_BYTES>>>(out);
}

// round 16
// speedup vs baseline: 1.6304x; 1.1082x over previous
#include <cuda_runtime.h>
#include <cuda_bf16.h>
#include <cuda_fp16.h>
#include <cstdint>

#define BATCH 4
#define SEQ   2048
#define EMB   1024
#define HS    64
#define MROWS (BATCH * SEQ)     // 8192
#define NCOMB 192               // Wq | Wk | Wv stacked

// Q pre-scale: HS^-0.5 * log2(e)  (softmax done in exp2 domain)
#define QSCALE 0.180336880111f

// ---------------------------------------------------------------------------
// Device scratch (no allocations allowed)
// ---------------------------------------------------------------------------
__device__ __half g_W16[NCOMB * EMB];  // single fp16 W (combined)
__device__ __half g_Qhi[MROWS * HS];   // fp16 hi/lo, pre-scaled by QSCALE
__device__ __half g_Qlo[MROWS * HS];
__device__ __half g_K16[MROWS * HS];   // single-pass fp16 K
__device__ __half g_V16[MROWS * HS];   // single-pass fp16 V
__device__ float g_Opart[4][MROWS * HS];
__device__ float g_mpart[4][MROWS];
__device__ float g_lpart[4][MROWS];
__device__ unsigned g_cnt[BATCH * 32];        // zero-init; self-resetting

// ---------------------------------------------------------------------------
// Helpers
// ---------------------------------------------------------------------------
static __device__ __forceinline__ unsigned smem_u32(const void* p) {
    unsigned a;
    asm("{ .reg .u64 t; cvta.to.shared.u64 t, %1; cvt.u32.u64 %0, t; }"
        : "=r"(a) : "l"(p));
    return a;
}
static __device__ __forceinline__ void ldm_x4(unsigned addr, unsigned r[4]) {
    asm volatile("ldmatrix.sync.aligned.m8n8.x4.shared.b16 {%0,%1,%2,%3}, [%4];"
                 : "=r"(r[0]), "=r"(r[1]), "=r"(r[2]), "=r"(r[3]) : "r"(addr));
}
static __device__ __forceinline__ void ldm_x4t(unsigned addr, unsigned r[4]) {
    asm volatile("ldmatrix.sync.aligned.m8n8.x4.trans.shared.b16 {%0,%1,%2,%3}, [%4];"
                 : "=r"(r[0]), "=r"(r[1]), "=r"(r[2]), "=r"(r[3]) : "r"(addr));
}
static __device__ __forceinline__ void mma_f16(float c[4], const unsigned a[4],
                                               const unsigned b[2]) {
    asm volatile(
        "mma.sync.aligned.m16n8k16.row.col.f32.f16.f16.f32 "
        "{%0,%1,%2,%3}, {%4,%5,%6,%7}, {%8,%9}, {%0,%1,%2,%3};"
        : "+f"(c[0]), "+f"(c[1]), "+f"(c[2]), "+f"(c[3])
        : "r"(a[0]), "r"(a[1]), "r"(a[2]), "r"(a[3]), "r"(b[0]), "r"(b[1]));
}
static __device__ __forceinline__ void split_hl_f16(float v0, float v1,
                                                    unsigned& hi, unsigned& lo) {
    __half h0 = __float2half(v0), h1 = __float2half(v1);
    __half2 h = __halves2half2(h0, h1);
    __half2 l = __halves2half2(__float2half(v0 - __half2float(h0)),
                               __float2half(v1 - __half2float(h1)));
    hi = reinterpret_cast<unsigned&>(h);
    lo = reinterpret_cast<unsigned&>(l);
}
static __device__ __forceinline__ unsigned pack_h2(float lo, float hi) {
    unsigned r;
    asm("cvt.rn.f16x2.f32 %0, %1, %2;" : "=r"(r) : "f"(hi), "f"(lo));
    return r;
}
static __device__ __forceinline__ float ex2(float x) {
    float y;
    asm("ex2.approx.ftz.f32 %0, %1;" : "=f"(y) : "f"(x));
    return y;
}
#define CP_ASYNC16(dst, src) \
    asm volatile("cp.async.cg.shared.global [%0], [%1], 16;" :: "r"(dst), "l"(src))
#define CP_COMMIT() asm volatile("cp.async.commit_group;")
#define CP_WAIT0()  asm volatile("cp.async.wait_group 0;")

// ---------------------------------------------------------------------------
// Kernel 0: W -> single fp16
// ---------------------------------------------------------------------------
__global__ __launch_bounds__(256) void wconv_kernel(
    const float* __restrict__ Wq, const float* __restrict__ Wk,
    const float* __restrict__ Wv)
{
    const int i = blockIdx.x * 256 + threadIdx.x;
    if (i >= NCOMB * EMB / 4) return;
    const int e = i * 4, row = e >> 10, col = e & 1023;
    const float* src = (row < 64)  ? (Wq + (size_t)row * EMB)
                     : (row < 128) ? (Wk + (size_t)(row - 64) * EMB)
                                   : (Wv + (size_t)(row - 128) * EMB);
    float4 v = *(const float4*)(src + col);
    uint2 p;
    p.x = pack_h2(v.x, v.y);
    p.y = pack_h2(v.z, v.w);
    ((uint2*)g_W16)[i] = p;
}

// ---------------------------------------------------------------------------
// Kernel 1: combined QKV GEMM, mma.sync fp16 SINGLE-pass (x fp16 x W fp16).
// BK=64, A+B double-buffered, ONE __syncthreads per chunk. smem 74KB ->
// 2 CTAs/SM. CTA 64x192, 256 thr, grid 128. fp32 accum; Q written hi/lo.
// ---------------------------------------------------------------------------
#define AST 72
#define A_STAGE_B 9216               // single fp16, one stage (64*72*2)
#define B_OFF     18432
#define B_BUF_BYTES 27648            // single fp16, one stage (192*72*2)
#define G_SMEM_BYTES (B_OFF + 2 * B_BUF_BYTES)   // 73728

__global__ __launch_bounds__(256, 2) void qkv_gemm_kernel(const float* __restrict__ x)
{
    extern __shared__ char smc[];
    const unsigned sbase = smem_u32(smc);
    const int tid  = threadIdx.x;
    const int wid  = tid >> 5;
    const int lane = tid & 31;
    const int wm   = wid & 1;
    const int wn   = wid >> 1;
    const int m0   = blockIdx.x * 64;

    float acc[2][6][4];
#pragma unroll
    for (int f = 0; f < 2; f++)
#pragma unroll
        for (int g = 0; g < 6; g++)
#pragma unroll
            for (int e = 0; e < 4; e++) acc[f][g][e] = 0.f;

    const int a_row = wm * 32 + (lane & 15);
    const int a_col = (lane >> 4) * 8;
    const int b_sub = lane >> 3;
    const int b_row = (b_sub >> 1) * 8 + (lane & 7);
    const int b_col = (b_sub & 1) * 8;

    // ---- prologue: A(0) -> smem stage 0; av <- A(1); cp.async B(0) ----
#pragma unroll
    for (int it = 0; it < 4; it++) {
        const int i = tid + it * 256;
        const int row = i >> 4, u = i & 15;
        float4 v = *(const float4*)(x + (size_t)(m0 + row) * EMB + u * 4);
        uint2 p;
        p.x = pack_h2(v.x, v.y);
        p.y = pack_h2(v.z, v.w);
        *(uint2*)(smc + (row * AST + u * 4) * 2) = p;
    }
    float4 av[4];
#pragma unroll
    for (int it = 0; it < 4; it++) {
        const int i = tid + it * 256;
        const int row = i >> 4, u = i & 15;
        av[it] = *(const float4*)(x + (size_t)(m0 + row) * EMB + 64 + u * 4);
    }
#pragma unroll
    for (int i = tid; i < 192 * 8; i += 256) {
        const int row = i >> 3, u = i & 7;
        const unsigned d = sbase + B_OFF + (unsigned)(row * AST + u * 8) * 2;
        CP_ASYNC16(d, g_W16 + (size_t)row * EMB + u * 8);
    }
    CP_COMMIT();

    for (int c = 0; c < 16; c++) {
        CP_WAIT0();            // drain B(c)
        __syncthreads();       // publish B(c) + A(c) stores; frees (c+1)&1 bufs

        if (c + 1 < 16) {
            char* abase = smc + ((c + 1) & 1) * A_STAGE_B;
#pragma unroll
            for (int it = 0; it < 4; it++) {
                const int i = tid + it * 256;
                const int row = i >> 4, u = i & 15;
                uint2 p;
                p.x = pack_h2(av[it].x, av[it].y);
                p.y = pack_h2(av[it].z, av[it].w);
                *(uint2*)(abase + (row * AST + u * 4) * 2) = p;
            }
            if (c + 2 < 16) {
                const int c2 = (c + 2) * 64;
#pragma unroll
                for (int it = 0; it < 4; it++) {
                    const int i = tid + it * 256;
                    const int row = i >> 4, u = i & 15;
                    av[it] = *(const float4*)(x + (size_t)(m0 + row) * EMB + c2 + u * 4);
                }
            }
            const int c1 = (c + 1) * 64;
            const unsigned bb = sbase + B_OFF + ((c + 1) & 1) * B_BUF_BYTES;
#pragma unroll
            for (int i = tid; i < 192 * 8; i += 256) {
                const int row = i >> 3, u = i & 7;
                const unsigned d = bb + (unsigned)(row * AST + u * 8) * 2;
                CP_ASYNC16(d, g_W16 + (size_t)row * EMB + c1 + u * 8);
            }
            CP_COMMIT();
        }

        // compute chunk c (single fp16 pass)
        const unsigned sA_u = sbase + (c & 1) * A_STAGE_B;
        const unsigned sB_u = sbase + B_OFF + (c & 1) * B_BUF_BYTES;

#pragma unroll
        for (int ks = 0; ks < 4; ks++) {
            unsigned ah[2][4], bh[6][2];
#pragma unroll
            for (int f = 0; f < 2; f++) {
                const unsigned off = ((a_row + f * 16) * AST + a_col + ks * 16) * 2;
                ldm_x4(sA_u + off, ah[f]);
            }
#pragma unroll
            for (int p = 0; p < 3; p++) {
                const unsigned off =
                    ((wn * 48 + p * 16 + b_row) * AST + b_col + ks * 16) * 2;
                unsigned t[4];
                ldm_x4(sB_u + off, t);
                bh[p * 2][0] = t[0]; bh[p * 2][1] = t[1];
                bh[p * 2 + 1][0] = t[2]; bh[p * 2 + 1][1] = t[3];
            }
#pragma unroll
            for (int f = 0; f < 2; f++)
#pragma unroll
                for (int g = 0; g < 6; g++)
                    mma_f16(acc[f][g], ah[f], bh[g]);
        }
    }

    // Epilogue: Q fp16 hi/lo (pre-scaled), K fp16, V fp16
#pragma unroll
    for (int g = 0; g < 6; g++) {
        const int nblk = wn * 48 + g * 8;
        const int coff = (nblk & 63) + (lane & 3) * 2;
#pragma unroll
        for (int f = 0; f < 2; f++) {
            const int row = m0 + wm * 32 + f * 16 + (lane >> 2);
            if (nblk < 64) {
                unsigned h0, l0, h1, l1;
                split_hl_f16(acc[f][g][0] * QSCALE, acc[f][g][1] * QSCALE, h0, l0);
                split_hl_f16(acc[f][g][2] * QSCALE, acc[f][g][3] * QSCALE, h1, l1);
                *(unsigned*)(g_Qhi + (size_t)row * HS + coff)       = h0;
                *(unsigned*)(g_Qlo + (size_t)row * HS + coff)       = l0;
                *(unsigned*)(g_Qhi + (size_t)(row + 8) * HS + coff) = h1;
                *(unsigned*)(g_Qlo + (size_t)(row + 8) * HS + coff) = l1;
            } else if (nblk < 128) {
                *(unsigned*)(g_K16 + (size_t)row * HS + coff) =
                    pack_h2(acc[f][g][0], acc[f][g][1]);
                *(unsigned*)(g_K16 + (size_t)(row + 8) * HS + coff) =
                    pack_h2(acc[f][g][2], acc[f][g][3]);
            } else {
                *(unsigned*)(g_V16 + (size_t)row * HS + coff) =
                    pack_h2(acc[f][g][0], acc[f][g][1]);
                *(unsigned*)(g_V16 + (size_t)(row + 8) * HS + coff) =
                    pack_h2(acc[f][g][2], acc[f][g][3]);
            }
        }
    }
}

// ---------------------------------------------------------------------------
// Kernel 2: causal flash attention (R15 config, unchanged — known passing).
// QK^T = Qhi*K + Qlo*K (2-pass fp16), PV fp16 single-pass. exp2 domain.
// K/V double-buffered, ONE sync per tile. Split-K <=9 tiles, grid 296 =
// one wave at 2 CTAs/SM. Fused last-CTA merge. Heavy-first.
// ---------------------------------------------------------------------------
#define FST 72
#define F_TILE (64 * FST)
#define F_TILE_B (F_TILE * 2)            // 9216
#define KV_STAGE_B (2 * F_TILE_B)        // K16, V16 = 18432
#define F_SMEM_BYTES (2 * F_TILE_B + 2 * KV_STAGE_B)   // 55296

__global__ __launch_bounds__(128, 2) void flash_kernel(float* __restrict__ out)
{
    extern __shared__ __half fsh[];
    __half* sQh = fsh;
    __half* sQl = sQh + F_TILE;
    __shared__ unsigned s_flag;

    // chunk -> (qblk, part, ns), ns = ceil((q+1)/9), heavy-first
    const int i = blockIdx.x;       // 0..73
    int qblk, part, ns;
    if (i < 20)      { qblk = 31 - (i >> 2); part = i & 3; ns = 4; }
    else if (i < 47) { int t = i - 20; qblk = 26 - t / 3; part = t % 3; ns = 3; }
    else if (i < 65) { int t = i - 47; qblk = 17 - (t >> 1); part = t & 1; ns = 2; }
    else             { int t = i - 65; qblk = 8 - t; part = 0; ns = 1; }
    const int b  = blockIdx.y;
    const int nt = qblk + 1;
    const int jb = part * nt / ns;
    const int je = (part + 1) * nt / ns;

    const int tid  = threadIdx.x;
    const int w    = tid >> 5;
    const int lane = tid & 31;
    const size_t base = (size_t)b * SEQ * HS;

    const unsigned sbase = smem_u32(fsh);
    const unsigned kv0   = sbase + 2 * F_TILE_B;

#pragma unroll
    for (int k = tid; k < 64 * 8; k += 128) {
        const int row = k >> 3, u = k & 7;
        const size_t gi = base + (size_t)(jb * 64 + row) * HS + u * 8;
        const unsigned d = kv0 + (unsigned)(row * FST + u * 8) * 2;
        CP_ASYNC16(d,            g_K16 + gi);
        CP_ASYNC16(d + F_TILE_B, g_V16 + gi);
    }
    CP_COMMIT();

#pragma unroll
    for (int k = tid; k < 64 * 8; k += 128) {
        const int row = k >> 3, u = k & 7;
        const size_t gi = base + (size_t)(qblk * 64 + row) * HS + u * 8;
        *(uint4*)(sQh + row * FST + u * 8) = *(const uint4*)(g_Qhi + gi);
        *(uint4*)(sQl + row * FST + u * 8) = *(const uint4*)(g_Qlo + gi);
    }
    __syncthreads();

    const unsigned sQh_u = sbase, sQl_u = sbase + F_TILE_B;
    unsigned qh[4][4], ql[4][4];
    {
        const int ar = w * 16 + (lane & 15);
        const int ac = (lane >> 4) * 8;
#pragma unroll
        for (int ks = 0; ks < 4; ks++) {
            const unsigned off = (ar * FST + ks * 16 + ac) * 2;
            ldm_x4(sQh_u + off, qh[ks]);
            ldm_x4(sQl_u + off, ql[ks]);
        }
    }

    float o[8][4];
#pragma unroll
    for (int nf = 0; nf < 8; nf++)
#pragma unroll
        for (int e = 0; e < 4; e++) o[nf][e] = 0.f;
    float mA = -1e30f, mB = -1e30f, lA = 0.f, lB = 0.f;

    const int b_sub = lane >> 3;
    const int kb_row = (b_sub >> 1) * 8 + (lane & 7);
    const int kb_col = (b_sub & 1) * 8;
    const int vb_row = (b_sub & 1) * 8 + (lane & 7);
    const int vb_col = (b_sub >> 1) * 8;

    for (int j = jb; j < je; j++) {
        const int cur = (j - jb) & 1;

        CP_WAIT0();
        __syncthreads();

        if (j + 1 < je) {
            const unsigned nb = kv0 + (cur ^ 1) * KV_STAGE_B;
#pragma unroll
            for (int k = tid; k < 64 * 8; k += 128) {
                const int row = k >> 3, u = k & 7;
                const size_t gi = base + (size_t)((j + 1) * 64 + row) * HS + u * 8;
                const unsigned d = nb + (unsigned)(row * FST + u * 8) * 2;
                CP_ASYNC16(d,            g_K16 + gi);
                CP_ASYNC16(d + F_TILE_B, g_V16 + gi);
            }
            CP_COMMIT();
        }

        const unsigned sK_u = kv0 + cur * KV_STAGE_B;
        const unsigned sV_u = sK_u + F_TILE_B;

        float s[8][4];
#pragma unroll
        for (int nf = 0; nf < 8; nf++)
#pragma unroll
            for (int e = 0; e < 4; e++) s[nf][e] = 0.f;

#pragma unroll
        for (int ks = 0; ks < 4; ks++) {
            unsigned kh[8][2];
#pragma unroll
            for (int np = 0; np < 4; np++) {
                const unsigned off = ((np * 16 + kb_row) * FST + ks * 16 + kb_col) * 2;
                unsigned t[4];
                ldm_x4(sK_u + off, t);
                kh[np * 2][0] = t[0]; kh[np * 2][1] = t[1];
                kh[np * 2 + 1][0] = t[2]; kh[np * 2 + 1][1] = t[3];
            }
#pragma unroll
            for (int nf = 0; nf < 8; nf++) {
                mma_f16(s[nf], qh[ks], kh[nf]);
                mma_f16(s[nf], ql[ks], kh[nf]);
            }
        }

        // Hoisted V-fragment loads (overlap softmax MUFU chain)
        unsigned vh[4][8][2];
#pragma unroll
        for (int ks = 0; ks < 4; ks++)
#pragma unroll
            for (int hp = 0; hp < 4; hp++) {
                const unsigned off = ((ks * 16 + vb_row) * FST + hp * 16 + vb_col) * 2;
                unsigned t[4];
                ldm_x4t(sV_u + off, t);
                vh[ks][hp * 2][0] = t[0]; vh[ks][hp * 2][1] = t[1];
                vh[ks][hp * 2 + 1][0] = t[2]; vh[ks][hp * 2 + 1][1] = t[3];
            }

        if (j == qblk) {
            const int rA = w * 16 + (lane >> 2);
            const int c0 = (lane & 3) * 2;
#pragma unroll
            for (int nf = 0; nf < 8; nf++) {
                const int c = nf * 8 + c0;
                if (c > rA)         s[nf][0] = -1e30f;
                if (c + 1 > rA)     s[nf][1] = -1e30f;
                if (c > rA + 8)     s[nf][2] = -1e30f;
                if (c + 1 > rA + 8) s[nf][3] = -1e30f;
            }
        }

        float tmA = -1e30f, tmB = -1e30f;
#pragma unroll
        for (int nf = 0; nf < 8; nf++) {
            tmA = fmaxf(tmA, fmaxf(s[nf][0], s[nf][1]));
            tmB = fmaxf(tmB, fmaxf(s[nf][2], s[nf][3]));
        }
#pragma unroll
        for (int off = 1; off < 4; off <<= 1) {
            tmA = fmaxf(tmA, __shfl_xor_sync(0xffffffffu, tmA, off));
            tmB = fmaxf(tmB, __shfl_xor_sync(0xffffffffu, tmB, off));
        }
        const float mnA = fmaxf(mA, tmA), mnB = fmaxf(mB, tmB);
        const float aA = ex2(mA - mnA), aB = ex2(mB - mnB);
        mA = mnA; mB = mnB;

        float sumA = 0.f, sumB = 0.f;
#pragma unroll
        for (int nf = 0; nf < 8; nf++) {
            s[nf][0] = ex2(s[nf][0] - mnA); sumA += s[nf][0];
            s[nf][1] = ex2(s[nf][1] - mnA); sumA += s[nf][1];
            s[nf][2] = ex2(s[nf][2] - mnB); sumB += s[nf][2];
            s[nf][3] = ex2(s[nf][3] - mnB); sumB += s[nf][3];
        }
#pragma unroll
        for (int off = 1; off < 4; off <<= 1) {
            sumA += __shfl_xor_sync(0xffffffffu, sumA, off);
            sumB += __shfl_xor_sync(0xffffffffu, sumB, off);
        }
        lA = lA * aA + sumA;
        lB = lB * aB + sumB;
#pragma unroll
        for (int nf = 0; nf < 8; nf++) {
            o[nf][0] *= aA; o[nf][1] *= aA;
            o[nf][2] *= aB; o[nf][3] *= aB;
        }

#pragma unroll
        for (int ks = 0; ks < 4; ks++) {
            unsigned ap[4];
            ap[0] = pack_h2(s[2 * ks][0],     s[2 * ks][1]);
            ap[1] = pack_h2(s[2 * ks][2],     s[2 * ks][3]);
            ap[2] = pack_h2(s[2 * ks + 1][0], s[2 * ks + 1][1]);
            ap[3] = pack_h2(s[2 * ks + 1][2], s[2 * ks + 1][3]);
#pragma unroll
            for (int nf = 0; nf < 8; nf++)
                mma_f16(o[nf], ap, vh[ks][nf]);
        }
    }

    const int rA = qblk * 64 + w * 16 + (lane >> 2);
    const size_t grA = (size_t)b * SEQ + rA;
    const size_t grB = grA + 8;
    const int c0 = (lane & 3) * 2;

    if (ns == 1) {
        const float invA = 1.f / lA, invB = 1.f / lB;
#pragma unroll
        for (int nf = 0; nf < 8; nf++) {
            const int c = nf * 8 + c0;
            *(float2*)(out + grA * HS + c) =
                make_float2(o[nf][0] * invA, o[nf][1] * invA);
            *(float2*)(out + grB * HS + c) =
                make_float2(o[nf][2] * invB, o[nf][3] * invB);
        }
        return;
    }

#pragma unroll
    for (int nf = 0; nf < 8; nf++) {
        const int c = nf * 8 + c0;
        *(float2*)(&g_Opart[part][grA * HS + c]) = make_float2(o[nf][0], o[nf][1]);
        *(float2*)(&g_Opart[part][grB * HS + c]) = make_float2(o[nf][2], o[nf][3]);
    }
    if ((lane & 3) == 0) {
        g_mpart[part][grA] = mA; g_lpart[part][grA] = lA;
        g_mpart[part][grB] = mB; g_lpart[part][grB] = lB;
    }

    __threadfence();
    if (tid == 0) {
        const unsigned old = atomicAdd(&g_cnt[b * 32 + qblk], 1);
        s_flag = (old == (unsigned)(ns - 1)) ? 1u : 0u;
    }
    __syncthreads();
    if (s_flag) {
        __threadfence();
#pragma unroll
        for (int it = 0; it < 8; it++) {
            const int slot = tid + it * 128;
            const int rl = slot >> 4, u = slot & 15;
            const size_t gr = (size_t)b * SEQ + qblk * 64 + rl;
            float m = -1e30f;
            for (int p = 0; p < ns; p++) m = fmaxf(m, g_mpart[p][gr]);
            float ap[4], den = 0.f;
            for (int p = 0; p < ns; p++) {
                ap[p] = ex2(g_mpart[p][gr] - m);
                den += g_lpart[p][gr] * ap[p];
            }
            const float inv = 1.f / den;
            float4 acc = make_float4(0.f, 0.f, 0.f, 0.f);
            for (int p = 0; p < ns; p++) {
                float4 v = ((const float4*)(g_Opart[p] + gr * HS))[u];
                acc.x += v.x * ap[p]; acc.y += v.y * ap[p];
                acc.z += v.z * ap[p]; acc.w += v.w * ap[p];
            }
            acc.x *= inv; acc.y *= inv; acc.z *= inv; acc.w *= inv;
            ((float4*)(out + gr * HS))[u] = acc;
        }
        __syncthreads();
        if (tid == 0) g_cnt[b * 32 + qblk] = 0;
    }
}

// ---------------------------------------------------------------------------

extern "C" void kernel_launch(void* const* d_in, const int* in_sizes, int n_in,
                              void* d_out, int out_size)
{
    const float* x  = (const float*)d_in[0];
    const float* Wq = (const float*)d_in[1];
    const float* Wk = (const float*)d_in[2];
    const float* Wv = (const float*)d_in[3];
    float* out      = (float*)d_out;
    (void)in_sizes; (void)n_in; (void)out_size;

    cudaFuncSetAttribute(qkv_gemm_kernel,
                         cudaFuncAttributeMaxDynamicSharedMemorySize, G_SMEM_BYTES);
    cudaFuncSetAttribute(flash_kernel,
                         cudaFuncAttributeMaxDynamicSharedMemorySize, F_SMEM_BYTES);

    wconv_kernel<<<(NCOMB * EMB / 4 + 255) / 256, 256>>>(Wq, Wk, Wv);
    qkv_gemm_kernel<<<MROWS / 64, 256, G_SMEM_BYTES>>>(x);
    flash_kernel<<<dim3(74, BATCH), 128, F_SMEM_BYTES>>>(out);
}

// round 17
// speedup vs baseline: 1.6959x; 1.0402x over previous
#include <cuda_runtime.h>
#include <cuda_bf16.h>
#include <cuda_fp16.h>
#include <cstdint>

#define BATCH 4
#define SEQ   2048
#define EMB   1024
#define HS    64
#define MROWS (BATCH * SEQ)     // 8192
#define NCOMB 192               // Wq | Wk | Wv stacked

// Q pre-scale: HS^-0.5 * log2(e)  (softmax done in exp2 domain)
#define QSCALE 0.180336880111f

// ---------------------------------------------------------------------------
// Device scratch (no allocations allowed)
// ---------------------------------------------------------------------------
__device__ __half g_W16[NCOMB * EMB];  // single fp16 W (combined)
__device__ __half g_Q16[MROWS * HS];   // single fp16 Q, pre-scaled by QSCALE
__device__ __half g_K16[MROWS * HS];   // single fp16 K
__device__ __half g_V16[MROWS * HS];   // single fp16 V
__device__ float g_Opart[4][MROWS * HS];
__device__ float g_mpart[4][MROWS];
__device__ float g_lpart[4][MROWS];
__device__ unsigned g_cnt[BATCH * 32];        // zero-init; self-resetting

// ---------------------------------------------------------------------------
// Helpers
// ---------------------------------------------------------------------------
static __device__ __forceinline__ unsigned smem_u32(const void* p) {
    unsigned a;
    asm("{ .reg .u64 t; cvta.to.shared.u64 t, %1; cvt.u32.u64 %0, t; }"
        : "=r"(a) : "l"(p));
    return a;
}
static __device__ __forceinline__ void ldm_x4(unsigned addr, unsigned r[4]) {
    asm volatile("ldmatrix.sync.aligned.m8n8.x4.shared.b16 {%0,%1,%2,%3}, [%4];"
                 : "=r"(r[0]), "=r"(r[1]), "=r"(r[2]), "=r"(r[3]) : "r"(addr));
}
static __device__ __forceinline__ void ldm_x4t(unsigned addr, unsigned r[4]) {
    asm volatile("ldmatrix.sync.aligned.m8n8.x4.trans.shared.b16 {%0,%1,%2,%3}, [%4];"
                 : "=r"(r[0]), "=r"(r[1]), "=r"(r[2]), "=r"(r[3]) : "r"(addr));
}
static __device__ __forceinline__ void mma_f16(float c[4], const unsigned a[4],
                                               const unsigned b[2]) {
    asm volatile(
        "mma.sync.aligned.m16n8k16.row.col.f32.f16.f16.f32 "
        "{%0,%1,%2,%3}, {%4,%5,%6,%7}, {%8,%9}, {%0,%1,%2,%3};"
        : "+f"(c[0]), "+f"(c[1]), "+f"(c[2]), "+f"(c[3])
        : "r"(a[0]), "r"(a[1]), "r"(a[2]), "r"(a[3]), "r"(b[0]), "r"(b[1]));
}
static __device__ __forceinline__ unsigned pack_h2(float lo, float hi) {
    unsigned r;
    asm("cvt.rn.f16x2.f32 %0, %1, %2;" : "=r"(r) : "f"(hi), "f"(lo));
    return r;
}
static __device__ __forceinline__ float ex2(float x) {
    float y;
    asm("ex2.approx.ftz.f32 %0, %1;" : "=f"(y) : "f"(x));
    return y;
}
#define CP_ASYNC16(dst, src) \
    asm volatile("cp.async.cg.shared.global [%0], [%1], 16;" :: "r"(dst), "l"(src))
#define CP_COMMIT() asm volatile("cp.async.commit_group;")
#define CP_WAIT0()  asm volatile("cp.async.wait_group 0;")

// ---------------------------------------------------------------------------
// Kernel 0: W -> single fp16
// ---------------------------------------------------------------------------
__global__ __launch_bounds__(256) void wconv_kernel(
    const float* __restrict__ Wq, const float* __restrict__ Wk,
    const float* __restrict__ Wv)
{
    const int i = blockIdx.x * 256 + threadIdx.x;
    if (i >= NCOMB * EMB / 4) return;
    const int e = i * 4, row = e >> 10, col = e & 1023;
    const float* src = (row < 64)  ? (Wq + (size_t)row * EMB)
                     : (row < 128) ? (Wk + (size_t)(row - 64) * EMB)
                                   : (Wv + (size_t)(row - 128) * EMB);
    float4 v = *(const float4*)(src + col);
    uint2 p;
    p.x = pack_h2(v.x, v.y);
    p.y = pack_h2(v.z, v.w);
    ((uint2*)g_W16)[i] = p;
}

// ---------------------------------------------------------------------------
// Kernel 1: combined QKV GEMM, mma.sync fp16 single-pass (R16 config).
// BK=64, A+B double-buffered, ONE __syncthreads per chunk. smem 74KB ->
// 2 CTAs/SM. CTA 64x192, 256 thr, grid 128. fp32 accum.
// Epilogue: Q fp16 single (pre-scaled), K fp16, V fp16.
// ---------------------------------------------------------------------------
#define AST 72
#define A_STAGE_B 9216               // single fp16, one stage (64*72*2)
#define B_OFF     18432
#define B_BUF_BYTES 27648            // single fp16, one stage (192*72*2)
#define G_SMEM_BYTES (B_OFF + 2 * B_BUF_BYTES)   // 73728

__global__ __launch_bounds__(256, 2) void qkv_gemm_kernel(const float* __restrict__ x)
{
    extern __shared__ char smc[];
    const unsigned sbase = smem_u32(smc);
    const int tid  = threadIdx.x;
    const int wid  = tid >> 5;
    const int lane = tid & 31;
    const int wm   = wid & 1;
    const int wn   = wid >> 1;
    const int m0   = blockIdx.x * 64;

    float acc[2][6][4];
#pragma unroll
    for (int f = 0; f < 2; f++)
#pragma unroll
        for (int g = 0; g < 6; g++)
#pragma unroll
            for (int e = 0; e < 4; e++) acc[f][g][e] = 0.f;

    const int a_row = wm * 32 + (lane & 15);
    const int a_col = (lane >> 4) * 8;
    const int b_sub = lane >> 3;
    const int b_row = (b_sub >> 1) * 8 + (lane & 7);
    const int b_col = (b_sub & 1) * 8;

    // ---- prologue: A(0) -> smem stage 0; av <- A(1); cp.async B(0) ----
#pragma unroll
    for (int it = 0; it < 4; it++) {
        const int i = tid + it * 256;
        const int row = i >> 4, u = i & 15;
        float4 v = *(const float4*)(x + (size_t)(m0 + row) * EMB + u * 4);
        uint2 p;
        p.x = pack_h2(v.x, v.y);
        p.y = pack_h2(v.z, v.w);
        *(uint2*)(smc + (row * AST + u * 4) * 2) = p;
    }
    float4 av[4];
#pragma unroll
    for (int it = 0; it < 4; it++) {
        const int i = tid + it * 256;
        const int row = i >> 4, u = i & 15;
        av[it] = *(const float4*)(x + (size_t)(m0 + row) * EMB + 64 + u * 4);
    }
#pragma unroll
    for (int i = tid; i < 192 * 8; i += 256) {
        const int row = i >> 3, u = i & 7;
        const unsigned d = sbase + B_OFF + (unsigned)(row * AST + u * 8) * 2;
        CP_ASYNC16(d, g_W16 + (size_t)row * EMB + u * 8);
    }
    CP_COMMIT();

    for (int c = 0; c < 16; c++) {
        CP_WAIT0();            // drain B(c)
        __syncthreads();       // publish B(c) + A(c) stores; frees (c+1)&1 bufs

        if (c + 1 < 16) {
            char* abase = smc + ((c + 1) & 1) * A_STAGE_B;
#pragma unroll
            for (int it = 0; it < 4; it++) {
                const int i = tid + it * 256;
                const int row = i >> 4, u = i & 15;
                uint2 p;
                p.x = pack_h2(av[it].x, av[it].y);
                p.y = pack_h2(av[it].z, av[it].w);
                *(uint2*)(abase + (row * AST + u * 4) * 2) = p;
            }
            if (c + 2 < 16) {
                const int c2 = (c + 2) * 64;
#pragma unroll
                for (int it = 0; it < 4; it++) {
                    const int i = tid + it * 256;
                    const int row = i >> 4, u = i & 15;
                    av[it] = *(const float4*)(x + (size_t)(m0 + row) * EMB + c2 + u * 4);
                }
            }
            const int c1 = (c + 1) * 64;
            const unsigned bb = sbase + B_OFF + ((c + 1) & 1) * B_BUF_BYTES;
#pragma unroll
            for (int i = tid; i < 192 * 8; i += 256) {
                const int row = i >> 3, u = i & 7;
                const unsigned d = bb + (unsigned)(row * AST + u * 8) * 2;
                CP_ASYNC16(d, g_W16 + (size_t)row * EMB + c1 + u * 8);
            }
            CP_COMMIT();
        }

        // compute chunk c (single fp16 pass)
        const unsigned sA_u = sbase + (c & 1) * A_STAGE_B;
        const unsigned sB_u = sbase + B_OFF + (c & 1) * B_BUF_BYTES;

#pragma unroll
        for (int ks = 0; ks < 4; ks++) {
            unsigned ah[2][4], bh[6][2];
#pragma unroll
            for (int f = 0; f < 2; f++) {
                const unsigned off = ((a_row + f * 16) * AST + a_col + ks * 16) * 2;
                ldm_x4(sA_u + off, ah[f]);
            }
#pragma unroll
            for (int p = 0; p < 3; p++) {
                const unsigned off =
                    ((wn * 48 + p * 16 + b_row) * AST + b_col + ks * 16) * 2;
                unsigned t[4];
                ldm_x4(sB_u + off, t);
                bh[p * 2][0] = t[0]; bh[p * 2][1] = t[1];
                bh[p * 2 + 1][0] = t[2]; bh[p * 2 + 1][1] = t[3];
            }
#pragma unroll
            for (int f = 0; f < 2; f++)
#pragma unroll
                for (int g = 0; g < 6; g++)
                    mma_f16(acc[f][g], ah[f], bh[g]);
        }
    }

    // Epilogue: Q fp16 single (pre-scaled), K fp16, V fp16
#pragma unroll
    for (int g = 0; g < 6; g++) {
        const int nblk = wn * 48 + g * 8;
        const int coff = (nblk & 63) + (lane & 3) * 2;
        __half* dst = (nblk < 64) ? g_Q16 : ((nblk < 128) ? g_K16 : g_V16);
        const float sc = (nblk < 64) ? QSCALE : 1.0f;
#pragma unroll
        for (int f = 0; f < 2; f++) {
            const int row = m0 + wm * 32 + f * 16 + (lane >> 2);
            *(unsigned*)(dst + (size_t)row * HS + coff) =
                pack_h2(acc[f][g][0] * sc, acc[f][g][1] * sc);
            *(unsigned*)(dst + (size_t)(row + 8) * HS + coff) =
                pack_h2(acc[f][g][2] * sc, acc[f][g][3] * sc);
        }
    }
}

// ---------------------------------------------------------------------------
// Kernel 2: causal flash attention. QK^T single-pass fp16 (Q and K fp16),
// PV single-pass fp16. exp2 domain. K/V double-buffered, ONE sync per
// tile. Split-K <=9 tiles, grid 296 = one wave at 2 CTAs/SM. Fused
// last-CTA merge. Heavy-first.
// ---------------------------------------------------------------------------
#define FST 72
#define F_TILE (64 * FST)
#define F_TILE_B (F_TILE * 2)            // 9216
#define KV_STAGE_B (2 * F_TILE_B)        // K16, V16 = 18432
#define F_SMEM_BYTES (F_TILE_B + 2 * KV_STAGE_B)   // 46080

__global__ __launch_bounds__(128, 2) void flash_kernel(float* __restrict__ out)
{
    extern __shared__ __half fsh[];
    __half* sQ = fsh;
    __shared__ unsigned s_flag;

    // chunk -> (qblk, part, ns), ns = ceil((q+1)/9), heavy-first
    const int i = blockIdx.x;       // 0..73
    int qblk, part, ns;
    if (i < 20)      { qblk = 31 - (i >> 2); part = i & 3; ns = 4; }
    else if (i < 47) { int t = i - 20; qblk = 26 - t / 3; part = t % 3; ns = 3; }
    else if (i < 65) { int t = i - 47; qblk = 17 - (t >> 1); part = t & 1; ns = 2; }
    else             { int t = i - 65; qblk = 8 - t; part = 0; ns = 1; }
    const int b  = blockIdx.y;
    const int nt = qblk + 1;
    const int jb = part * nt / ns;
    const int je = (part + 1) * nt / ns;

    const int tid  = threadIdx.x;
    const int w    = tid >> 5;
    const int lane = tid & 31;
    const size_t base = (size_t)b * SEQ * HS;

    const unsigned sbase = smem_u32(fsh);
    const unsigned kv0   = sbase + F_TILE_B;

#pragma unroll
    for (int k = tid; k < 64 * 8; k += 128) {
        const int row = k >> 3, u = k & 7;
        const size_t gi = base + (size_t)(jb * 64 + row) * HS + u * 8;
        const unsigned d = kv0 + (unsigned)(row * FST + u * 8) * 2;
        CP_ASYNC16(d,            g_K16 + gi);
        CP_ASYNC16(d + F_TILE_B, g_V16 + gi);
    }
    CP_COMMIT();

#pragma unroll
    for (int k = tid; k < 64 * 8; k += 128) {
        const int row = k >> 3, u = k & 7;
        const size_t gi = base + (size_t)(qblk * 64 + row) * HS + u * 8;
        *(uint4*)(sQ + row * FST + u * 8) = *(const uint4*)(g_Q16 + gi);
    }
    __syncthreads();

    unsigned qh[4][4];
    {
        const int ar = w * 16 + (lane & 15);
        const int ac = (lane >> 4) * 8;
#pragma unroll
        for (int ks = 0; ks < 4; ks++) {
            const unsigned off = (ar * FST + ks * 16 + ac) * 2;
            ldm_x4(sbase + off, qh[ks]);
        }
    }

    float o[8][4];
#pragma unroll
    for (int nf = 0; nf < 8; nf++)
#pragma unroll
        for (int e = 0; e < 4; e++) o[nf][e] = 0.f;
    float mA = -1e30f, mB = -1e30f, lA = 0.f, lB = 0.f;

    const int b_sub = lane >> 3;
    const int kb_row = (b_sub >> 1) * 8 + (lane & 7);
    const int kb_col = (b_sub & 1) * 8;
    const int vb_row = (b_sub & 1) * 8 + (lane & 7);
    const int vb_col = (b_sub >> 1) * 8;

    for (int j = jb; j < je; j++) {
        const int cur = (j - jb) & 1;

        CP_WAIT0();
        __syncthreads();

        if (j + 1 < je) {
            const unsigned nb = kv0 + (cur ^ 1) * KV_STAGE_B;
#pragma unroll
            for (int k = tid; k < 64 * 8; k += 128) {
                const int row = k >> 3, u = k & 7;
                const size_t gi = base + (size_t)((j + 1) * 64 + row) * HS + u * 8;
                const unsigned d = nb + (unsigned)(row * FST + u * 8) * 2;
                CP_ASYNC16(d,            g_K16 + gi);
                CP_ASYNC16(d + F_TILE_B, g_V16 + gi);
            }
            CP_COMMIT();
        }

        const unsigned sK_u = kv0 + cur * KV_STAGE_B;
        const unsigned sV_u = sK_u + F_TILE_B;

        float s[8][4];
#pragma unroll
        for (int nf = 0; nf < 8; nf++)
#pragma unroll
            for (int e = 0; e < 4; e++) s[nf][e] = 0.f;

#pragma unroll
        for (int ks = 0; ks < 4; ks++) {
            unsigned kh[8][2];
#pragma unroll
            for (int np = 0; np < 4; np++) {
                const unsigned off = ((np * 16 + kb_row) * FST + ks * 16 + kb_col) * 2;
                unsigned t[4];
                ldm_x4(sK_u + off, t);
                kh[np * 2][0] = t[0]; kh[np * 2][1] = t[1];
                kh[np * 2 + 1][0] = t[2]; kh[np * 2 + 1][1] = t[3];
            }
#pragma unroll
            for (int nf = 0; nf < 8; nf++)
                mma_f16(s[nf], qh[ks], kh[nf]);
        }

        // Hoisted V-fragment loads (overlap softmax MUFU chain)
        unsigned vh[4][8][2];
#pragma unroll
        for (int ks = 0; ks < 4; ks++)
#pragma unroll
            for (int hp = 0; hp < 4; hp++) {
                const unsigned off = ((ks * 16 + vb_row) * FST + hp * 16 + vb_col) * 2;
                unsigned t[4];
                ldm_x4t(sV_u + off, t);
                vh[ks][hp * 2][0] = t[0]; vh[ks][hp * 2][1] = t[1];
                vh[ks][hp * 2 + 1][0] = t[2]; vh[ks][hp * 2 + 1][1] = t[3];
            }

        if (j == qblk) {
            const int rA = w * 16 + (lane >> 2);
            const int c0 = (lane & 3) * 2;
#pragma unroll
            for (int nf = 0; nf < 8; nf++) {
                const int c = nf * 8 + c0;
                if (c > rA)         s[nf][0] = -1e30f;
                if (c + 1 > rA)     s[nf][1] = -1e30f;
                if (c > rA + 8)     s[nf][2] = -1e30f;
                if (c + 1 > rA + 8) s[nf][3] = -1e30f;
            }
        }

        float tmA = -1e30f, tmB = -1e30f;
#pragma unroll
        for (int nf = 0; nf < 8; nf++) {
            tmA = fmaxf(tmA, fmaxf(s[nf][0], s[nf][1]));
            tmB = fmaxf(tmB, fmaxf(s[nf][2], s[nf][3]));
        }
#pragma unroll
        for (int off = 1; off < 4; off <<= 1) {
            tmA = fmaxf(tmA, __shfl_xor_sync(0xffffffffu, tmA, off));
            tmB = fmaxf(tmB, __shfl_xor_sync(0xffffffffu, tmB, off));
        }
        const float mnA = fmaxf(mA, tmA), mnB = fmaxf(mB, tmB);
        const float aA = ex2(mA - mnA), aB = ex2(mB - mnB);
        mA = mnA; mB = mnB;

        float sumA = 0.f, sumB = 0.f;
#pragma unroll
        for (int nf = 0; nf < 8; nf++) {
            s[nf][0] = ex2(s[nf][0] - mnA); sumA += s[nf][0];
            s[nf][1] = ex2(s[nf][1] - mnA); sumA += s[nf][1];
            s[nf][2] = ex2(s[nf][2] - mnB); sumB += s[nf][2];
            s[nf][3] = ex2(s[nf][3] - mnB); sumB += s[nf][3];
        }
#pragma unroll
        for (int off = 1; off < 4; off <<= 1) {
            sumA += __shfl_xor_sync(0xffffffffu, sumA, off);
            sumB += __shfl_xor_sync(0xffffffffu, sumB, off);
        }
        lA = lA * aA + sumA;
        lB = lB * aB + sumB;
#pragma unroll
        for (int nf = 0; nf < 8; nf++) {
            o[nf][0] *= aA; o[nf][1] *= aA;
            o[nf][2] *= aB; o[nf][3] *= aB;
        }

#pragma unroll
        for (int ks = 0; ks < 4; ks++) {
            unsigned ap[4];
            ap[0] = pack_h2(s[2 * ks][0],     s[2 * ks][1]);
            ap[1] = pack_h2(s[2 * ks][2],     s[2 * ks][3]);
            ap[2] = pack_h2(s[2 * ks + 1][0], s[2 * ks + 1][1]);
            ap[3] = pack_h2(s[2 * ks + 1][2], s[2 * ks + 1][3]);
#pragma unroll
            for (int nf = 0; nf < 8; nf++)
                mma_f16(o[nf], ap, vh[ks][nf]);
        }
    }

    const int rA = qblk * 64 + w * 16 + (lane >> 2);
    const size_t grA = (size_t)b * SEQ + rA;
    const size_t grB = grA + 8;
    const int c0 = (lane & 3) * 2;

    if (ns == 1) {
        const float invA = 1.f / lA, invB = 1.f / lB;
#pragma unroll
        for (int nf = 0; nf < 8; nf++) {
            const int c = nf * 8 + c0;
            *(float2*)(out + grA * HS + c) =
                make_float2(o[nf][0] * invA, o[nf][1] * invA);
            *(float2*)(out + grB * HS + c) =
                make_float2(o[nf][2] * invB, o[nf][3] * invB);
        }
        return;
    }

#pragma unroll
    for (int nf = 0; nf < 8; nf++) {
        const int c = nf * 8 + c0;
        *(float2*)(&g_Opart[part][grA * HS + c]) = make_float2(o[nf][0], o[nf][1]);
        *(float2*)(&g_Opart[part][grB * HS + c]) = make_float2(o[nf][2], o[nf][3]);
    }
    if ((lane & 3) == 0) {
        g_mpart[part][grA] = mA; g_lpart[part][grA] = lA;
        g_mpart[part][grB] = mB; g_lpart[part][grB] = lB;
    }

    __threadfence();
    if (tid == 0) {
        const unsigned old = atomicAdd(&g_cnt[b * 32 + qblk], 1);
        s_flag = (old == (unsigned)(ns - 1)) ? 1u : 0u;
    }
    __syncthreads();
    if (s_flag) {
        __threadfence();
#pragma unroll
        for (int it = 0; it < 8; it++) {
            const int slot = tid + it * 128;
            const int rl = slot >> 4, u = slot & 15;
            const size_t gr = (size_t)b * SEQ + qblk * 64 + rl;
            float m = -1e30f;
            for (int p = 0; p < ns; p++) m = fmaxf(m, g_mpart[p][gr]);
            float ap[4], den = 0.f;
            for (int p = 0; p < ns; p++) {
                ap[p] = ex2(g_mpart[p][gr] - m);
                den += g_lpart[p][gr] * ap[p];
            }
            const float inv = 1.f / den;
            float4 acc = make_float4(0.f, 0.f, 0.f, 0.f);
            for (int p = 0; p < ns; p++) {
                float4 v = ((const float4*)(g_Opart[p] + gr * HS))[u];
                acc.x += v.x * ap[p]; acc.y += v.y * ap[p];
                acc.z += v.z * ap[p]; acc.w += v.w * ap[p];
            }
            acc.x *= inv; acc.y *= inv; acc.z *= inv; acc.w *= inv;
            ((float4*)(out + gr * HS))[u] = acc;
        }
        __syncthreads();
        if (tid == 0) g_cnt[b * 32 + qblk] = 0;
    }
}

// ---------------------------------------------------------------------------

extern "C" void kernel_launch(void* const* d_in, const int* in_sizes, int n_in,
                              void* d_out, int out_size)
{
    const float* x  = (const float*)d_in[0];
    const float* Wq = (const float*)d_in[1];
    const float* Wk = (const float*)d_in[2];
    const float* Wv = (const float*)d_in[3];
    float* out      = (float*)d_out;
    (void)in_sizes; (void)n_in; (void)out_size;

    cudaFuncSetAttribute(qkv_gemm_kernel,
                         cudaFuncAttributeMaxDynamicSharedMemorySize, G_SMEM_BYTES);
    cudaFuncSetAttribute(flash_kernel,
                         cudaFuncAttributeMaxDynamicSharedMemorySize, F_SMEM_BYTES);

    wconv_kernel<<<(NCOMB * EMB / 4 + 255) / 256, 256>>>(Wq, Wk, Wv);
    qkv_gemm_kernel<<<MROWS / 64, 256, G_SMEM_BYTES>>>(x);
    flash_kernel<<<dim3(74, BATCH), 128, F_SMEM_BYTES>>>(out);
}